// round 13
// baseline (speedup 1.0000x reference)
#include <cuda_runtime.h>
#include <cuda_bf16.h>

#define HDIM   256
#define GDIM   1024      // 4*H
#define BATCH  64
#define SEQ    512
#define NRD    10        // 5 branches * 2 directions
#define NBR    5
#define EDIM   300
#define ADIM   512       // 2*H
#define VOCAB  50000
#define EKP    152       // padded kpair count for EDIM=300 (150 real + 2 zero)

typedef unsigned long long ull;
typedef unsigned int u32;

// ---------------- scratch (device globals; no allocation allowed) ----------------
__device__ float g_P  [335544320];               // [NRD][SEQ][BATCH][GDIM]
__device__ ull   g_HS2[41943040];                // [NRD][SEQ][BATCH][128]  h pre-split
__device__ ull   g_H2 [2][NRD][BATCH][HDIM/2];   // ping-pong h pre-split
__device__ ull   g_E2 [VOCAB * EKP];             // emb pre-split
__device__ ull   g_W2 [NRD * GDIM * EKP];        // Wih pre-split
__device__ ull   g_Wa2[NBR * ADIM * 256];        // Wa pre-split
__device__ float g_ATT[NBR][BATCH][ADIM];
__device__ float g_logit[NBR][BATCH][SEQ];
__device__ float g_attw [NBR][BATCH][SEQ];
__device__ unsigned g_cnt[NRD];
__device__ unsigned g_ready[NRD * 256];          // per (rec, spair): tiles done (goal 16)

__device__ __forceinline__ float fsigm(float x) { return 1.0f / (1.0f + __expf(-x)); }
__device__ __forceinline__ float ftanh(float x) { return 1.0f - 2.0f / (__expf(2.0f * x) + 1.0f); }

// bf16 2-term split of a float pair -> (hi word | lo word << 32)
__device__ __forceinline__ ull split2(float2 v) {
    __nv_bfloat162 h = __floats2bfloat162_rn(v.x, v.y);
    float r0 = v.x - __bfloat162float(h.x);
    float r1 = v.y - __bfloat162float(h.y);
    __nv_bfloat162 l = __floats2bfloat162_rn(r0, r1);
    u32 hw = *(u32*)&h;
    u32 lw = *(u32*)&l;
    return (ull)hw | ((ull)lw << 32);
}

#define MMA_BF16(c, a, b) \
    asm volatile("mma.sync.aligned.m16n8k16.row.col.f32.bf16.bf16.f32 " \
                 "{%0,%1,%2,%3}, {%4,%5,%6,%7}, {%8,%9}, {%0,%1,%2,%3};" \
                 : "+f"((c)[0]), "+f"((c)[1]), "+f"((c)[2]), "+f"((c)[3]) \
                 : "r"((a)[0]), "r"((a)[1]), "r"((a)[2]), "r"((a)[3]), \
                   "r"((b)[0]), "r"((b)[1]))

// ---------------- init -----------------------------------------------------------
__global__ void k_init() {
    int idx = blockIdx.x * blockDim.x + threadIdx.x;
    ull* Hz = &g_H2[0][0][0][0];
    if (idx < 2 * NRD * BATCH * (HDIM / 2)) Hz[idx] = 0ull;
    if (idx < NBR * BATCH * SEQ)            ((float*)g_logit)[idx] = 0.0f;
    if (idx < NRD)                          g_cnt[idx] = 0u;
    if (idx < NRD * 256)                    g_ready[idx] = 0u;
}

// ---------------- pre-split tables ------------------------------------------------
__global__ void k_presplit_emb(const float* __restrict__ emb) {
    long long idx = (long long)blockIdx.x * blockDim.x + threadIdx.x;
    if (idx >= (long long)VOCAB * EKP) return;
    int row = (int)(idx / EKP), kp = (int)(idx % EKP);
    float2 v = (kp < 150) ? *(const float2*)(emb + (size_t)row * EDIM + 2 * kp)
                          : make_float2(0.0f, 0.0f);
    g_E2[idx] = split2(v);
}
__global__ void k_presplit_wih(const float* __restrict__ Wih_f, const float* __restrict__ Wih_b) {
    long long idx = (long long)blockIdx.x * blockDim.x + threadIdx.x;
    if (idx >= (long long)NRD * GDIM * EKP) return;
    int kp = (int)(idx % EKP);
    int row = (int)((idx / EKP) % GDIM);
    int rd = (int)(idx / ((long long)GDIM * EKP));
    int branch = rd >> 1, dir = rd & 1;
    const float* W = (dir ? Wih_b : Wih_f) + (size_t)branch * GDIM * EDIM;
    float2 v = (kp < 150) ? *(const float2*)(W + (size_t)row * EDIM + 2 * kp)
                          : make_float2(0.0f, 0.0f);
    g_W2[idx] = split2(v);
}
__global__ void k_presplit_wa(const float* __restrict__ Wa) {
    long long idx = (long long)blockIdx.x * blockDim.x + threadIdx.x;
    if (idx >= (long long)NBR * ADIM * 256) return;
    g_Wa2[idx] = split2(*(const float2*)(Wa + 2 * idx));
}

// ---------------- phase 1: P = emb[x] @ Wih.T + (bih+bhh)  [HMMA, pre-split] ------
// grid (x: rd*16+ntile = 160, y: mtile-slot = 256, y slowest). mtile mirrored for
// backward recs so production order matches scan consumption. Releases g_ready.
__global__ void k_inputproj(const int* __restrict__ x,
                            const float* __restrict__ bih_f, const float* __restrict__ bhh_f,
                            const float* __restrict__ bih_b, const float* __restrict__ bhh_b) {
    __shared__ __align__(8) u32 As_s[128 * 20];   // [m][kp*2 + {hi,lo}]
    __shared__ __align__(8) u32 Bs_s[64 * 20];
    __shared__ int tok[128];
    int rd = blockIdx.x >> 4, ntile = blockIdx.x & 15;
    int branch = rd >> 1, dir = rd & 1;
    int mtile = dir ? (255 - blockIdx.y) : blockIdx.y;
    const float* bi  = (dir ? bih_b : bih_f) + branch * GDIM;
    const float* bh  = (dir ? bhh_b : bhh_f) + branch * GDIM;
    int tid = threadIdx.x;
    int m0 = mtile * 128, n0 = ntile * 64;
    if (tid < 128) {
        int m = m0 + tid;
        tok[tid] = x[(m & 63) * SEQ + (m >> 6)];
    }
    int lane = tid & 31, wid = tid >> 5;
    int g = lane >> 2, tg = lane & 3;
    int wm = wid & 3, wn = wid >> 2;
    int mbase = wm * 32, nbase = wn * 32;
    float C[2][4][4];
#pragma unroll
    for (int mt = 0; mt < 2; mt++)
#pragma unroll
        for (int nt = 0; nt < 4; nt++)
#pragma unroll
            for (int q = 0; q < 4; q++) C[mt][nt][q] = 0.0f;
    __syncthreads();

    for (int k0 = 0; k0 < 304; k0 += 16) {
        int kb = k0 >> 1;   // kpair base
#pragma unroll
        for (int i = 0; i < 4; i++) {
            int task = tid + i * 256;
            int m = task >> 3, kp = task & 7;
            *(ull*)&As_s[m * 20 + 2 * kp] = g_E2[(size_t)tok[m] * EKP + kb + kp];
        }
#pragma unroll
        for (int i = 0; i < 2; i++) {
            int task = tid + i * 256;
            int n = task >> 3, kp = task & 7;
            *(ull*)&Bs_s[n * 20 + 2 * kp] = g_W2[((size_t)rd * GDIM + n0 + n) * EKP + kb + kp];
        }
        __syncthreads();
        u32 Ahi[2][4], Alo[2][4], Bhi[4][2], Blo[4][2];
#pragma unroll
        for (int mt = 0; mt < 2; mt++) {
            int r0 = mbase + mt * 16 + g;
            ull v0 = *(const ull*)&As_s[r0 * 20 + 2 * tg];
            ull v1 = *(const ull*)&As_s[(r0 + 8) * 20 + 2 * tg];
            ull v2 = *(const ull*)&As_s[r0 * 20 + 2 * (tg + 4)];
            ull v3 = *(const ull*)&As_s[(r0 + 8) * 20 + 2 * (tg + 4)];
            Ahi[mt][0] = (u32)v0; Alo[mt][0] = (u32)(v0 >> 32);
            Ahi[mt][1] = (u32)v1; Alo[mt][1] = (u32)(v1 >> 32);
            Ahi[mt][2] = (u32)v2; Alo[mt][2] = (u32)(v2 >> 32);
            Ahi[mt][3] = (u32)v3; Alo[mt][3] = (u32)(v3 >> 32);
        }
#pragma unroll
        for (int nt = 0; nt < 4; nt++) {
            int n = nbase + nt * 8 + g;
            ull v0 = *(const ull*)&Bs_s[n * 20 + 2 * tg];
            ull v1 = *(const ull*)&Bs_s[n * 20 + 2 * (tg + 4)];
            Bhi[nt][0] = (u32)v0; Blo[nt][0] = (u32)(v0 >> 32);
            Bhi[nt][1] = (u32)v1; Blo[nt][1] = (u32)(v1 >> 32);
        }
#pragma unroll
        for (int mt = 0; mt < 2; mt++)
#pragma unroll
            for (int nt = 0; nt < 4; nt++) {
                MMA_BF16(C[mt][nt], Ahi[mt], Bhi[nt]);
                MMA_BF16(C[mt][nt], Ahi[mt], Blo[nt]);
                MMA_BF16(C[mt][nt], Alo[mt], Bhi[nt]);
            }
        __syncthreads();
    }
#pragma unroll
    for (int mt = 0; mt < 2; mt++)
#pragma unroll
        for (int rr = 0; rr < 2; rr++) {
            int m = m0 + mbase + mt * 16 + g + rr * 8;
            float* Pp = g_P + (((size_t)rd * SEQ + (m >> 6)) * BATCH + (m & 63)) * GDIM + n0 + nbase;
#pragma unroll
            for (int nt = 0; nt < 4; nt++) {
                int nl = nt * 8 + 2 * tg;
                int nf = n0 + nbase + nl;
                float2 o;
                o.x = C[mt][nt][rr * 2 + 0] + bi[nf] + bh[nf];
                o.y = C[mt][nt][rr * 2 + 1] + bi[nf + 1] + bh[nf + 1];
                *(float2*)(Pp + nl) = o;
            }
        }
    // publish this tile (release orders the P stores)
    __syncthreads();
    if (tid == 0)
        asm volatile("red.release.gpu.global.add.u32 [%0], %1;"
                     :: "l"(&g_ready[rd * 256 + mtile]), "r"(1u) : "memory");
}

// ---------------- phase 2: persistent recurrent scan  [bf16-split HMMA] -----------
#define A_CHUNK 1032            // words/chunk: 64 rows * 16 + 8 pad
#define B_CHUNK 2056            // words/chunk: 128 rows * 16 + 8 pad
#define SCAN_SMEM ((16 * A_CHUNK + 16 * B_CHUNK) * 4)   // 197,632 B

__global__ void __launch_bounds__(256, 1)
k_scan(const float* __restrict__ Whh_f, const float* __restrict__ Whh_b) {
    extern __shared__ __align__(16) u32 smw[];
    u32* Bw = smw;                     // Whh split, resident
    u32* Aw = smw + 16 * B_CHUNK;      // h split, restaged per step

    int rd = blockIdx.x >> 3;
    int blk = blockIdx.x & 7;
    int j0 = blk * 32;
    int branch = rd >> 1, dir = rd & 1;
    const float* W = (dir ? Whh_b : Whh_f) + (size_t)branch * GDIM * HDIM;
    int tid = threadIdx.x;
    int lane = tid & 31, wid = tid >> 5;
    int g = lane >> 2, tg = lane & 3;
    int wm = wid & 3, wn = wid >> 2;
    int mbase = wm * 16, nbase = wn * 64;
    int xg = g << 1;                   // xor swizzle key (rows ≡ g mod 8)

    // ---- stage Whh slice (permuted rows, bf16 split), one time ----
    for (int p = tid; p < 128 * 128; p += 256) {
        int r = p >> 7;                 // n' 0..127
        int kpair = p & 127;
        int wnn = r >> 6, w = r & 63;
        int gate = w >> 4, jl = wnn * 16 + (w & 15);
        float2 v = *(const float2*)&W[(size_t)(gate * HDIM + j0 + jl) * HDIM + 2 * kpair];
        int idx = (kpair >> 3) * B_CHUNK + r * 16 + ((2 * (kpair & 7)) ^ ((r & 7) << 1));
        *(ull*)&Bw[idx] = split2(v);
    }
    float c[2][4];                      // [rr][jh*2+q]
#pragma unroll
    for (int a = 0; a < 2; a++)
#pragma unroll
        for (int b = 0; b < 4; b++) c[a][b] = 0.0f;
    __syncthreads();

    for (int t = 0; t < SEQ; ++t) {
        int sidx = dir ? (SEQ - 1 - t) : t;
        // wait for producers (spair changes only on even t)
        if ((t & 1) == 0) {
            if (tid == 0) {
                unsigned v;
                const unsigned* f = &g_ready[rd * 256 + (sidx >> 1)];
                do {
                    asm volatile("ld.acquire.gpu.global.u32 %0, [%1];" : "=r"(v) : "l"(f) : "memory");
                } while (v < 16u);
            }
            __syncthreads();
        }
        // prefetch P preacts for this thread's 32 output units
        const float* Pb = g_P + ((size_t)rd * SEQ + sidx) * BATCH * GDIM;
        float2 Pr[2][2][4];             // [rr][jh][gate]
#pragma unroll
        for (int rr = 0; rr < 2; rr++) {
            int b = mbase + g + 8 * rr;
#pragma unroll
            for (int jh = 0; jh < 2; jh++) {
                int j = j0 + wn * 16 + jh * 8 + 2 * tg;
#pragma unroll
                for (int gate = 0; gate < 4; gate++)
                    Pr[rr][jh][gate] = *(const float2*)&Pb[(size_t)b * GDIM + gate * HDIM + j];
            }
        }

        // stage h (pre-split in global -> no math) into Aw
        int par = t & 1;
        const ull* Hs = &g_H2[par][rd][0][0];
#pragma unroll
        for (int i = 0; i < 32; i++) {
            int p = tid + i * 256;
            int b = p >> 7, kpair = p & 127;
            ull v = __ldcv(&Hs[b * 128 + kpair]);
            int idx = (kpair >> 3) * A_CHUNK + b * 16 + ((2 * (kpair & 7)) ^ ((b & 7) << 1));
            *(ull*)&Aw[idx] = v;
        }
        __syncthreads();

        float C[8][4];
#pragma unroll
        for (int nt = 0; nt < 8; nt++)
#pragma unroll
            for (int q = 0; q < 4; q++) C[nt][q] = 0.0f;

#pragma unroll 4
        for (int chunk = 0; chunk < 16; chunk++) {
            const u32* Ac = Aw + chunk * A_CHUNK;
            const u32* Bc = Bw + chunk * B_CHUNK;
            u32 Ahi[4], Alo[4];
            {
                int r0 = mbase + g;
                ull v0 = *(const ull*)&Ac[r0 * 16 + ((2 * tg) ^ xg)];
                ull v1 = *(const ull*)&Ac[(r0 + 8) * 16 + ((2 * tg) ^ xg)];
                ull v2 = *(const ull*)&Ac[r0 * 16 + ((2 * (tg + 4)) ^ xg)];
                ull v3 = *(const ull*)&Ac[(r0 + 8) * 16 + ((2 * (tg + 4)) ^ xg)];
                Ahi[0] = (u32)v0; Alo[0] = (u32)(v0 >> 32);
                Ahi[1] = (u32)v1; Alo[1] = (u32)(v1 >> 32);
                Ahi[2] = (u32)v2; Alo[2] = (u32)(v2 >> 32);
                Ahi[3] = (u32)v3; Alo[3] = (u32)(v3 >> 32);
            }
#pragma unroll
            for (int nt = 0; nt < 8; nt++) {
                int n = nbase + nt * 8 + g;
                ull v0 = *(const ull*)&Bc[n * 16 + ((2 * tg) ^ xg)];
                ull v1 = *(const ull*)&Bc[n * 16 + ((2 * (tg + 4)) ^ xg)];
                u32 Bhi[2], Blo[2];
                Bhi[0] = (u32)v0; Blo[0] = (u32)(v0 >> 32);
                Bhi[1] = (u32)v1; Blo[1] = (u32)(v1 >> 32);
                MMA_BF16(C[nt], Ahi, Bhi);
                MMA_BF16(C[nt], Ahi, Blo);
                MMA_BF16(C[nt], Alo, Bhi);
            }
        }

        // epilogue: gates + cell update; h stored pre-split to BOTH g_H2 and g_HS2
        ull* HSo = g_HS2 + ((size_t)rd * SEQ + sidx) * BATCH * 128;
        ull* Hn = &g_H2[par ^ 1][rd][0][0];
#pragma unroll
        for (int rr = 0; rr < 2; rr++) {
            int b = mbase + g + 8 * rr;
#pragma unroll
            for (int jh = 0; jh < 2; jh++) {
                int j = j0 + wn * 16 + jh * 8 + 2 * tg;
                float iv0 = C[0 + jh][rr * 2 + 0] + Pr[rr][jh][0].x;
                float fv0 = C[2 + jh][rr * 2 + 0] + Pr[rr][jh][1].x;
                float gv0 = C[4 + jh][rr * 2 + 0] + Pr[rr][jh][2].x;
                float ov0 = C[6 + jh][rr * 2 + 0] + Pr[rr][jh][3].x;
                float iv1 = C[0 + jh][rr * 2 + 1] + Pr[rr][jh][0].y;
                float fv1 = C[2 + jh][rr * 2 + 1] + Pr[rr][jh][1].y;
                float gv1 = C[4 + jh][rr * 2 + 1] + Pr[rr][jh][2].y;
                float ov1 = C[6 + jh][rr * 2 + 1] + Pr[rr][jh][3].y;
                float cn0 = fsigm(fv0) * c[rr][jh * 2 + 0] + fsigm(iv0) * ftanh(gv0);
                float cn1 = fsigm(fv1) * c[rr][jh * 2 + 1] + fsigm(iv1) * ftanh(gv1);
                c[rr][jh * 2 + 0] = cn0;
                c[rr][jh * 2 + 1] = cn1;
                float2 hv;
                hv.x = fsigm(ov0) * ftanh(cn0);
                hv.y = fsigm(ov1) * ftanh(cn1);
                ull sp = split2(hv);
                Hn[b * 128 + (j >> 1)] = sp;
                HSo[(size_t)b * 128 + (j >> 1)] = sp;
            }
        }
        // inter-block step barrier: bar -> release-red -> acquire-poll
        __syncthreads();
        if (tid == 0) {
            asm volatile("red.release.gpu.global.add.u32 [%0], %1;"
                         :: "l"(&g_cnt[rd]), "r"(1u) : "memory");
            unsigned target = 8u * (unsigned)(t + 1), v;
            do {
                asm volatile("ld.acquire.gpu.global.u32 %0, [%1];"
                             : "=r"(v) : "l"(&g_cnt[rd]) : "memory");
            } while (v < target);
        }
        __syncthreads();
    }
}

// ---------------- phase 3a: attention logits  [HMMA, pre-split operands] ----------
__global__ void k_logits(const float* __restrict__ ba, const float* __restrict__ watt) {
    __shared__ __align__(8) u32 As_s[128 * 20];
    __shared__ __align__(8) u32 Bs_s[64 * 20];
    int mtile = blockIdx.x, ntile = blockIdx.y, br = blockIdx.z;
    int tid = threadIdx.x;
    int m0 = mtile * 128, n0 = ntile * 64;
    int lane = tid & 31, wid = tid >> 5;
    int g = lane >> 2, tg = lane & 3;
    int wm = wid & 3, wn = wid >> 2;
    int mbase = wm * 32, nbase = wn * 32;
    float C[2][4][4];
#pragma unroll
    for (int mt = 0; mt < 2; mt++)
#pragma unroll
        for (int nt = 0; nt < 4; nt++)
#pragma unroll
            for (int q = 0; q < 4; q++) C[mt][nt][q] = 0.0f;

    for (int k0 = 0; k0 < ADIM; k0 += 16) {
        int rdh = 2 * br + (k0 >> 8);
        int kbl = (k0 & 255) >> 1;
#pragma unroll
        for (int i = 0; i < 4; i++) {
            int task = tid + i * 256;
            int m = task >> 3, kp = task & 7;
            int mm = m0 + m;
            *(ull*)&As_s[m * 20 + 2 * kp] =
                g_HS2[(((size_t)rdh * SEQ + (mm >> 6)) * BATCH + (mm & 63)) * 128 + kbl + kp];
        }
#pragma unroll
        for (int i = 0; i < 2; i++) {
            int task = tid + i * 256;
            int n = task >> 3, kp = task & 7;
            *(ull*)&Bs_s[n * 20 + 2 * kp] =
                g_Wa2[((size_t)br * ADIM + n0 + n) * 256 + (k0 >> 1) + kp];
        }
        __syncthreads();
        u32 Ahi[2][4], Alo[2][4], Bhi[4][2], Blo[4][2];
#pragma unroll
        for (int mt = 0; mt < 2; mt++) {
            int r0 = mbase + mt * 16 + g;
            ull v0 = *(const ull*)&As_s[r0 * 20 + 2 * tg];
            ull v1 = *(const ull*)&As_s[(r0 + 8) * 20 + 2 * tg];
            ull v2 = *(const ull*)&As_s[r0 * 20 + 2 * (tg + 4)];
            ull v3 = *(const ull*)&As_s[(r0 + 8) * 20 + 2 * (tg + 4)];
            Ahi[mt][0] = (u32)v0; Alo[mt][0] = (u32)(v0 >> 32);
            Ahi[mt][1] = (u32)v1; Alo[mt][1] = (u32)(v1 >> 32);
            Ahi[mt][2] = (u32)v2; Alo[mt][2] = (u32)(v2 >> 32);
            Ahi[mt][3] = (u32)v3; Alo[mt][3] = (u32)(v3 >> 32);
        }
#pragma unroll
        for (int nt = 0; nt < 4; nt++) {
            int n = nbase + nt * 8 + g;
            ull v0 = *(const ull*)&Bs_s[n * 20 + 2 * tg];
            ull v1 = *(const ull*)&Bs_s[n * 20 + 2 * (tg + 4)];
            Bhi[nt][0] = (u32)v0; Blo[nt][0] = (u32)(v0 >> 32);
            Bhi[nt][1] = (u32)v1; Blo[nt][1] = (u32)(v1 >> 32);
        }
#pragma unroll
        for (int mt = 0; mt < 2; mt++)
#pragma unroll
            for (int nt = 0; nt < 4; nt++) {
                MMA_BF16(C[mt][nt], Ahi[mt], Bhi[nt]);
                MMA_BF16(C[mt][nt], Ahi[mt], Blo[nt]);
                MMA_BF16(C[mt][nt], Alo[mt], Bhi[nt]);
            }
        __syncthreads();
    }
#pragma unroll
    for (int mt = 0; mt < 2; mt++) {
        float p0 = 0.0f, p1 = 0.0f;
#pragma unroll
        for (int nt = 0; nt < 4; nt++) {
            int nf = n0 + nbase + nt * 8 + 2 * tg;
            float b0 = ba[br * ADIM + nf], w0 = watt[br * ADIM + nf];
            float b1 = ba[br * ADIM + nf + 1], w1 = watt[br * ADIM + nf + 1];
            p0 += ftanh(C[mt][nt][0] + b0) * w0 + ftanh(C[mt][nt][1] + b1) * w1;
            p1 += ftanh(C[mt][nt][2] + b0) * w0 + ftanh(C[mt][nt][3] + b1) * w1;
        }
        p0 += __shfl_xor_sync(0xffffffffu, p0, 1);
        p0 += __shfl_xor_sync(0xffffffffu, p0, 2);
        p1 += __shfl_xor_sync(0xffffffffu, p1, 1);
        p1 += __shfl_xor_sync(0xffffffffu, p1, 2);
        if (tg == 0) {
            int m = m0 + mbase + mt * 16 + g;
            atomicAdd(&g_logit[br][m & 63][m >> 6], p0);
            int m2 = m + 8;
            atomicAdd(&g_logit[br][m2 & 63][m2 >> 6], p1);
        }
    }
}

// ---------------- phase 3b: softmax over S -------------------------------------
__global__ void k_softmax() {
    int br = blockIdx.x >> 6, b = blockIdx.x & 63;
    __shared__ float red[256];
    const float* L = &g_logit[br][b][0];
    int tid = threadIdx.x;
    red[tid] = fmaxf(L[tid], L[tid + 256]); __syncthreads();
    for (int o = 128; o > 0; o >>= 1) { if (tid < o) red[tid] = fmaxf(red[tid], red[tid + o]); __syncthreads(); }
    float mx = red[0]; __syncthreads();
    float e0 = __expf(L[tid] - mx), e1 = __expf(L[tid + 256] - mx);
    red[tid] = e0 + e1; __syncthreads();
    for (int o = 128; o > 0; o >>= 1) { if (tid < o) red[tid] += red[tid + o]; __syncthreads(); }
    float inv = 1.0f / red[0];
    g_attw[br][b][tid] = e0 * inv;
    g_attw[br][b][tid + 256] = e1 * inv;
}

// ---------------- phase 3c: attention-weighted sum (reconstruct h = hi+lo) -------
__global__ void k_attsum() {
    int b = blockIdx.x, br = blockIdx.y;
    int d = threadIdx.x;
    __shared__ float aw[512];
    aw[d] = g_attw[br][b][d];
    __syncthreads();
    int rdh = (d < HDIM) ? (2 * br) : (2 * br + 1);
    int dd = d & 255;
    int kpair = dd >> 1, e = dd & 1;
    const ull* base = g_HS2 + (size_t)rdh * SEQ * BATCH * 128 + (size_t)b * 128 + kpair;
    float a0 = 0.0f, a1 = 0.0f;
    for (int s = 0; s < SEQ; s += 2) {
        ull v0 = base[(size_t)s * BATCH * 128];
        ull v1 = base[(size_t)(s + 1) * BATCH * 128];
        u32 hw0 = (u32)v0, lw0 = (u32)(v0 >> 32);
        u32 hw1 = (u32)v1, lw1 = (u32)(v1 >> 32);
        u32 sh = e ? 0 : 16;
        float h0 = __uint_as_float((hw0 << sh) & 0xffff0000u) + __uint_as_float((lw0 << sh) & 0xffff0000u);
        float h1 = __uint_as_float((hw1 << sh) & 0xffff0000u) + __uint_as_float((lw1 << sh) & 0xffff0000u);
        a0 = fmaf(aw[s],     h0, a0);
        a1 = fmaf(aw[s + 1], h1, a1);
    }
    g_ATT[br][b][d] = a0 + a1;
}

// ---------------- phase 4: routed final FC --------------------------------------
__global__ void k_final(const int* __restrict__ z, const float* __restrict__ Wfc,
                        const float* __restrict__ bfc, float* __restrict__ out) {
    int b = blockIdx.x;
    int tid = threadIdx.x;
    int zb = z[b];
    __shared__ float red0[256], red1[256];
    float a0 = 0.0f, a1 = 0.0f;
    for (int k = tid; k < 1024; k += 256) {
        float v = (k < 512) ? g_ATT[zb + 1][b][k] : g_ATT[0][b][k - 512];
        a0 = fmaf(v, Wfc[k], a0);
        a1 = fmaf(v, Wfc[1024 + k], a1);
    }
    red0[tid] = a0; red1[tid] = a1; __syncthreads();
    for (int o = 128; o > 0; o >>= 1) {
        if (tid < o) { red0[tid] += red0[tid + o]; red1[tid] += red1[tid + o]; }
        __syncthreads();
    }
    if (tid == 0) {
        out[b * 2 + 0] = red0[0] + bfc[0];
        out[b * 2 + 1] = red1[0] + bfc[1];
    }
}

// ---------------- copy general + specifics into d_out ---------------------------
__global__ void k_copyout(float* __restrict__ out) {
    int idx = blockIdx.x * blockDim.x + threadIdx.x;
    if (idx < NBR * BATCH * ADIM) out[128 + idx] = (&g_ATT[0][0][0])[idx];
}

// ---------------- launcher -------------------------------------------------------
extern "C" void kernel_launch(void* const* d_in, const int* in_sizes, int n_in,
                              void* d_out, int out_size) {
    const int*   x     = (const int*)  d_in[0];
    const int*   z     = (const int*)  d_in[1];
    const float* emb   = (const float*)d_in[2];
    const float* Wih_f = (const float*)d_in[3];
    const float* Whh_f = (const float*)d_in[4];
    const float* bih_f = (const float*)d_in[5];
    const float* bhh_f = (const float*)d_in[6];
    const float* Wih_b = (const float*)d_in[7];
    const float* Whh_b = (const float*)d_in[8];
    const float* bih_b = (const float*)d_in[9];
    const float* bhh_b = (const float*)d_in[10];
    const float* Wa    = (const float*)d_in[11];
    const float* ba    = (const float*)d_in[12];
    const float* watt  = (const float*)d_in[13];
    const float* Wfc   = (const float*)d_in[14];
    const float* bfc   = (const float*)d_in[15];
    float* out = (float*)d_out;

    // one-time infra: scan on HIGH-priority stream launched FIRST; producer LOW.
    static cudaStream_t sHi = nullptr, sLo = nullptr;
    static cudaEvent_t evA = nullptr, evScan = nullptr, evProd = nullptr;
    if (sHi == nullptr) {
        int least = 0, greatest = 0;
        cudaDeviceGetStreamPriorityRange(&least, &greatest);
        cudaStreamCreateWithPriority(&sHi, cudaStreamNonBlocking, greatest);
        cudaStreamCreateWithPriority(&sLo, cudaStreamNonBlocking, least);
        cudaEventCreateWithFlags(&evA, cudaEventDisableTiming);
        cudaEventCreateWithFlags(&evScan, cudaEventDisableTiming);
        cudaEventCreateWithFlags(&evProd, cudaEventDisableTiming);
    }
    cudaFuncSetAttribute(k_scan, cudaFuncAttributeMaxDynamicSharedMemorySize, SCAN_SMEM);

    k_init<<<1280, 256>>>();
    k_presplit_emb<<<(VOCAB * EKP + 255) / 256, 256>>>(emb);
    k_presplit_wih<<<(NRD * GDIM * EKP + 255) / 256, 256>>>(Wih_f, Wih_b);
    k_presplit_wa<<<(NBR * ADIM * 256 + 255) / 256, 256>>>(Wa);
    cudaEventRecord(evA, 0);
    cudaStreamWaitEvent(sHi, evA, 0);
    cudaStreamWaitEvent(sLo, evA, 0);
    // scan FIRST (80 blocks claim their SMs), then producers fill the rest
    k_scan<<<80, 256, SCAN_SMEM, sHi>>>(Whh_f, Whh_b);
    k_inputproj<<<dim3(160, 256), 256, 0, sLo>>>(x, bih_f, bhh_f, bih_b, bhh_b);
    cudaEventRecord(evScan, sHi);
    cudaEventRecord(evProd, sLo);
    cudaStreamWaitEvent(0, evScan, 0);
    cudaStreamWaitEvent(0, evProd, 0);
    k_logits<<<dim3(256, 8, 5), 256>>>(ba, watt);
    k_softmax<<<320, 256>>>();
    k_attsum<<<dim3(64, 5), 512>>>();
    k_final<<<64, 256>>>(z, Wfc, bfc, out);
    k_copyout<<<640, 256>>>(out);
}

// round 14
// speedup vs baseline: 1.2261x; 1.2261x over previous
#include <cuda_runtime.h>
#include <cuda_bf16.h>

#define HDIM   256
#define GDIM   1024      // 4*H
#define BATCH  64
#define SEQ    512
#define NRD    10        // 5 branches * 2 directions
#define NBR    5
#define EDIM   300
#define ADIM   512       // 2*H
#define VOCAB  50000
#define EKP    152       // padded kpair count for EDIM=300 (150 real + 2 zero)

typedef unsigned long long ull;
typedef unsigned int u32;

// ---------------- scratch (device globals; no allocation allowed) ----------------
__device__ float g_P  [335544320];               // [NRD][SEQ][BATCH][GDIM]
__device__ ull   g_HS2[41943040];                // [NRD][SEQ][BATCH][128]  h pre-split
__device__ ull   g_E2 [VOCAB * EKP];             // emb pre-split
__device__ ull   g_W2 [NRD * GDIM * EKP];        // Wih pre-split
__device__ ull   g_Wa2[NBR * ADIM * 256];        // Wa pre-split
__device__ float g_ATT[NBR][BATCH][ADIM];
__device__ float g_logit[NBR][BATCH][SEQ];
__device__ float g_attw [NBR][BATCH][SEQ];
__device__ unsigned g_cnt[NRD];

__device__ __forceinline__ float fsigm(float x) { return 1.0f / (1.0f + __expf(-x)); }
__device__ __forceinline__ float ftanh(float x) { return 1.0f - 2.0f / (__expf(2.0f * x) + 1.0f); }

// bf16 2-term split of a float pair -> (hi word | lo word << 32)
__device__ __forceinline__ ull split2(float2 v) {
    __nv_bfloat162 h = __floats2bfloat162_rn(v.x, v.y);
    float r0 = v.x - __bfloat162float(h.x);
    float r1 = v.y - __bfloat162float(h.y);
    __nv_bfloat162 l = __floats2bfloat162_rn(r0, r1);
    u32 hw = *(u32*)&h;
    u32 lw = *(u32*)&l;
    return (ull)hw | ((ull)lw << 32);
}

#define MMA_BF16(c, a, b) \
    asm volatile("mma.sync.aligned.m16n8k16.row.col.f32.bf16.bf16.f32 " \
                 "{%0,%1,%2,%3}, {%4,%5,%6,%7}, {%8,%9}, {%0,%1,%2,%3};" \
                 : "+f"((c)[0]), "+f"((c)[1]), "+f"((c)[2]), "+f"((c)[3]) \
                 : "r"((a)[0]), "r"((a)[1]), "r"((a)[2]), "r"((a)[3]), \
                   "r"((b)[0]), "r"((b)[1]))

// ---------------- init -----------------------------------------------------------
__global__ void k_init() {
    int idx = blockIdx.x * blockDim.x + threadIdx.x;
    if (idx < NBR * BATCH * SEQ) ((float*)g_logit)[idx] = 0.0f;
    if (idx < NRD)               g_cnt[idx] = 0u;
}

// ---------------- pre-split tables ------------------------------------------------
__global__ void k_presplit_emb(const float* __restrict__ emb) {
    long long idx = (long long)blockIdx.x * blockDim.x + threadIdx.x;
    if (idx >= (long long)VOCAB * EKP) return;
    int row = (int)(idx / EKP), kp = (int)(idx % EKP);
    float2 v = (kp < 150) ? *(const float2*)(emb + (size_t)row * EDIM + 2 * kp)
                          : make_float2(0.0f, 0.0f);
    g_E2[idx] = split2(v);
}
__global__ void k_presplit_wih(const float* __restrict__ Wih_f, const float* __restrict__ Wih_b) {
    long long idx = (long long)blockIdx.x * blockDim.x + threadIdx.x;
    if (idx >= (long long)NRD * GDIM * EKP) return;
    int kp = (int)(idx % EKP);
    int row = (int)((idx / EKP) % GDIM);
    int rd = (int)(idx / ((long long)GDIM * EKP));
    int branch = rd >> 1, dir = rd & 1;
    const float* W = (dir ? Wih_b : Wih_f) + (size_t)branch * GDIM * EDIM;
    float2 v = (kp < 150) ? *(const float2*)(W + (size_t)row * EDIM + 2 * kp)
                          : make_float2(0.0f, 0.0f);
    g_W2[idx] = split2(v);
}
__global__ void k_presplit_wa(const float* __restrict__ Wa) {
    long long idx = (long long)blockIdx.x * blockDim.x + threadIdx.x;
    if (idx >= (long long)NBR * ADIM * 256) return;
    g_Wa2[idx] = split2(*(const float2*)(Wa + 2 * idx));
}

// ---------------- phase 1: P = emb[x] @ Wih.T + bias  [HMMA, double-buffered] -----
__global__ void k_inputproj(const int* __restrict__ x,
                            const float* __restrict__ bih_f, const float* __restrict__ bhh_f,
                            const float* __restrict__ bih_b, const float* __restrict__ bhh_b) {
    __shared__ __align__(8) u32 As_s[2][128 * 20];
    __shared__ __align__(8) u32 Bs_s[2][64 * 20];
    __shared__ int tok[128];
    int mtile = blockIdx.x, ntile = blockIdx.y, rd = blockIdx.z;
    int branch = rd >> 1, dir = rd & 1;
    const float* bi  = (dir ? bih_b : bih_f) + branch * GDIM;
    const float* bh  = (dir ? bhh_b : bhh_f) + branch * GDIM;
    int tid = threadIdx.x;
    int m0 = mtile * 128, n0 = ntile * 64;
    if (tid < 128) {
        int m = m0 + tid;
        tok[tid] = x[(m & 63) * SEQ + (m >> 6)];
    }
    int lane = tid & 31, wid = tid >> 5;
    int g = lane >> 2, tg = lane & 3;
    int wm = wid & 3, wn = wid >> 2;
    int mbase = wm * 32, nbase = wn * 32;
    float C[2][4][4];
#pragma unroll
    for (int mt = 0; mt < 2; mt++)
#pragma unroll
        for (int nt = 0; nt < 4; nt++)
#pragma unroll
            for (int q = 0; q < 4; q++) C[mt][nt][q] = 0.0f;
    __syncthreads();

    // prologue: stage chunk 0 into buffer 0
    {
#pragma unroll
        for (int i = 0; i < 4; i++) {
            int task = tid + i * 256;
            int m = task >> 3, kp = task & 7;
            *(ull*)&As_s[0][m * 20 + 2 * kp] = g_E2[(size_t)tok[m] * EKP + kp];
        }
#pragma unroll
        for (int i = 0; i < 2; i++) {
            int task = tid + i * 256;
            int n = task >> 3, kp = task & 7;
            *(ull*)&Bs_s[0][n * 20 + 2 * kp] = g_W2[((size_t)rd * GDIM + n0 + n) * EKP + kp];
        }
    }
    __syncthreads();

    int buf = 0;
    for (int k0 = 0; k0 < 304; k0 += 16) {
        if (k0 + 16 < 304) {
            int kb = (k0 + 16) >> 1;
#pragma unroll
            for (int i = 0; i < 4; i++) {
                int task = tid + i * 256;
                int m = task >> 3, kp = task & 7;
                *(ull*)&As_s[buf ^ 1][m * 20 + 2 * kp] = g_E2[(size_t)tok[m] * EKP + kb + kp];
            }
#pragma unroll
            for (int i = 0; i < 2; i++) {
                int task = tid + i * 256;
                int n = task >> 3, kp = task & 7;
                *(ull*)&Bs_s[buf ^ 1][n * 20 + 2 * kp] = g_W2[((size_t)rd * GDIM + n0 + n) * EKP + kb + kp];
            }
        }
        const u32* Ac = As_s[buf];
        const u32* Bc = Bs_s[buf];
        u32 Ahi[2][4], Alo[2][4], Bhi[4][2], Blo[4][2];
#pragma unroll
        for (int mt = 0; mt < 2; mt++) {
            int r0 = mbase + mt * 16 + g;
            ull v0 = *(const ull*)&Ac[r0 * 20 + 2 * tg];
            ull v1 = *(const ull*)&Ac[(r0 + 8) * 20 + 2 * tg];
            ull v2 = *(const ull*)&Ac[r0 * 20 + 2 * (tg + 4)];
            ull v3 = *(const ull*)&Ac[(r0 + 8) * 20 + 2 * (tg + 4)];
            Ahi[mt][0] = (u32)v0; Alo[mt][0] = (u32)(v0 >> 32);
            Ahi[mt][1] = (u32)v1; Alo[mt][1] = (u32)(v1 >> 32);
            Ahi[mt][2] = (u32)v2; Alo[mt][2] = (u32)(v2 >> 32);
            Ahi[mt][3] = (u32)v3; Alo[mt][3] = (u32)(v3 >> 32);
        }
#pragma unroll
        for (int nt = 0; nt < 4; nt++) {
            int n = nbase + nt * 8 + g;
            ull v0 = *(const ull*)&Bc[n * 20 + 2 * tg];
            ull v1 = *(const ull*)&Bc[n * 20 + 2 * (tg + 4)];
            Bhi[nt][0] = (u32)v0; Blo[nt][0] = (u32)(v0 >> 32);
            Bhi[nt][1] = (u32)v1; Blo[nt][1] = (u32)(v1 >> 32);
        }
#pragma unroll
        for (int mt = 0; mt < 2; mt++)
#pragma unroll
            for (int nt = 0; nt < 4; nt++) {
                MMA_BF16(C[mt][nt], Ahi[mt], Bhi[nt]);
                MMA_BF16(C[mt][nt], Ahi[mt], Blo[nt]);
                MMA_BF16(C[mt][nt], Alo[mt], Bhi[nt]);
            }
        __syncthreads();
        buf ^= 1;
    }
#pragma unroll
    for (int mt = 0; mt < 2; mt++)
#pragma unroll
        for (int rr = 0; rr < 2; rr++) {
            int m = m0 + mbase + mt * 16 + g + rr * 8;
            float* Pp = g_P + (((size_t)rd * SEQ + (m >> 6)) * BATCH + (m & 63)) * GDIM + n0 + nbase;
#pragma unroll
            for (int nt = 0; nt < 4; nt++) {
                int nl = nt * 8 + 2 * tg;
                int nf = n0 + nbase + nl;
                float2 o;
                o.x = C[mt][nt][rr * 2 + 0] + bi[nf] + bh[nf];
                o.y = C[mt][nt][rr * 2 + 1] + bi[nf + 1] + bh[nf + 1];
                *(float2*)(Pp + nl) = o;
            }
        }
}

// ---------------- phase 2: persistent recurrent scan  [bf16-split HMMA] -----------
// h(t-1) read directly from g_HS2[rd][sidx_prev] (same [b][kpair] layout);
// no separate ping-pong buffer. t==0 stages zeros.
#define A_CHUNK 1032            // words/chunk: 64 rows * 16 + 8 pad
#define B_CHUNK 2056            // words/chunk: 128 rows * 16 + 8 pad
#define SCAN_SMEM ((16 * A_CHUNK + 16 * B_CHUNK) * 4)   // 197,632 B

__global__ void __launch_bounds__(256, 1)
k_scan(const float* __restrict__ Whh_f, const float* __restrict__ Whh_b) {
    extern __shared__ __align__(16) u32 smw[];
    u32* Bw = smw;                     // Whh split, resident
    u32* Aw = smw + 16 * B_CHUNK;      // h split, restaged per step

    int rd = blockIdx.x >> 3;
    int blk = blockIdx.x & 7;
    int j0 = blk * 32;
    int branch = rd >> 1, dir = rd & 1;
    const float* W = (dir ? Whh_b : Whh_f) + (size_t)branch * GDIM * HDIM;
    int tid = threadIdx.x;
    int lane = tid & 31, wid = tid >> 5;
    int g = lane >> 2, tg = lane & 3;
    int wm = wid & 3, wn = wid >> 2;
    int mbase = wm * 16, nbase = wn * 64;
    int xg = g << 1;                   // xor swizzle key (rows ≡ g mod 8)

    // ---- stage Whh slice (permuted rows, bf16 split), one time ----
    for (int p = tid; p < 128 * 128; p += 256) {
        int r = p >> 7;                 // n' 0..127
        int kpair = p & 127;
        int wnn = r >> 6, w = r & 63;
        int gate = w >> 4, jl = wnn * 16 + (w & 15);
        float2 v = *(const float2*)&W[(size_t)(gate * HDIM + j0 + jl) * HDIM + 2 * kpair];
        int idx = (kpair >> 3) * B_CHUNK + r * 16 + ((2 * (kpair & 7)) ^ ((r & 7) << 1));
        *(ull*)&Bw[idx] = split2(v);
    }
    float c[2][4];                      // [rr][jh*2+q]
#pragma unroll
    for (int a = 0; a < 2; a++)
#pragma unroll
        for (int b = 0; b < 4; b++) c[a][b] = 0.0f;
    __syncthreads();

    for (int t = 0; t < SEQ; ++t) {
        int sidx = dir ? (SEQ - 1 - t) : t;
        // prefetch P preacts for this thread's 32 output units
        const float* Pb = g_P + ((size_t)rd * SEQ + sidx) * BATCH * GDIM;
        float2 Pr[2][2][4];             // [rr][jh][gate]
#pragma unroll
        for (int rr = 0; rr < 2; rr++) {
            int b = mbase + g + 8 * rr;
#pragma unroll
            for (int jh = 0; jh < 2; jh++) {
                int j = j0 + wn * 16 + jh * 8 + 2 * tg;
#pragma unroll
                for (int gate = 0; gate < 4; gate++)
                    Pr[rr][jh][gate] = *(const float2*)&Pb[(size_t)b * GDIM + gate * HDIM + j];
            }
        }

        // stage h(t-1) from g_HS2[sidx_prev] (zeros at t==0)
        if (t == 0) {
#pragma unroll
            for (int i = 0; i < 32; i++) {
                int p = tid + i * 256;
                int b = p >> 7, kpair = p & 127;
                int idx = (kpair >> 3) * A_CHUNK + b * 16 + ((2 * (kpair & 7)) ^ ((b & 7) << 1));
                *(ull*)&Aw[idx] = 0ull;
            }
        } else {
            int sidx_prev = dir ? (SEQ - t) : (t - 1);
            const ull* Hs = g_HS2 + ((size_t)rd * SEQ + sidx_prev) * BATCH * 128;
#pragma unroll
            for (int i = 0; i < 32; i++) {
                int p = tid + i * 256;
                int b = p >> 7, kpair = p & 127;
                ull v = __ldcv(&Hs[b * 128 + kpair]);
                int idx = (kpair >> 3) * A_CHUNK + b * 16 + ((2 * (kpair & 7)) ^ ((b & 7) << 1));
                *(ull*)&Aw[idx] = v;
            }
        }
        __syncthreads();

        float C[8][4];
#pragma unroll
        for (int nt = 0; nt < 8; nt++)
#pragma unroll
            for (int q = 0; q < 4; q++) C[nt][q] = 0.0f;

#pragma unroll 4
        for (int chunk = 0; chunk < 16; chunk++) {
            const u32* Ac = Aw + chunk * A_CHUNK;
            const u32* Bc = Bw + chunk * B_CHUNK;
            u32 Ahi[4], Alo[4];
            {
                int r0 = mbase + g;
                ull v0 = *(const ull*)&Ac[r0 * 16 + ((2 * tg) ^ xg)];
                ull v1 = *(const ull*)&Ac[(r0 + 8) * 16 + ((2 * tg) ^ xg)];
                ull v2 = *(const ull*)&Ac[r0 * 16 + ((2 * (tg + 4)) ^ xg)];
                ull v3 = *(const ull*)&Ac[(r0 + 8) * 16 + ((2 * (tg + 4)) ^ xg)];
                Ahi[0] = (u32)v0; Alo[0] = (u32)(v0 >> 32);
                Ahi[1] = (u32)v1; Alo[1] = (u32)(v1 >> 32);
                Ahi[2] = (u32)v2; Alo[2] = (u32)(v2 >> 32);
                Ahi[3] = (u32)v3; Alo[3] = (u32)(v3 >> 32);
            }
#pragma unroll
            for (int nt = 0; nt < 8; nt++) {
                int n = nbase + nt * 8 + g;
                ull v0 = *(const ull*)&Bc[n * 16 + ((2 * tg) ^ xg)];
                ull v1 = *(const ull*)&Bc[n * 16 + ((2 * (tg + 4)) ^ xg)];
                u32 Bhi[2], Blo[2];
                Bhi[0] = (u32)v0; Blo[0] = (u32)(v0 >> 32);
                Bhi[1] = (u32)v1; Blo[1] = (u32)(v1 >> 32);
                MMA_BF16(C[nt], Ahi, Bhi);
                MMA_BF16(C[nt], Ahi, Blo);
                MMA_BF16(C[nt], Alo, Bhi);
            }
        }

        // epilogue: gates + cell update; h stored pre-split to g_HS2 only
        ull* HSo = g_HS2 + ((size_t)rd * SEQ + sidx) * BATCH * 128;
#pragma unroll
        for (int rr = 0; rr < 2; rr++) {
            int b = mbase + g + 8 * rr;
#pragma unroll
            for (int jh = 0; jh < 2; jh++) {
                int j = j0 + wn * 16 + jh * 8 + 2 * tg;
                float iv0 = C[0 + jh][rr * 2 + 0] + Pr[rr][jh][0].x;
                float fv0 = C[2 + jh][rr * 2 + 0] + Pr[rr][jh][1].x;
                float gv0 = C[4 + jh][rr * 2 + 0] + Pr[rr][jh][2].x;
                float ov0 = C[6 + jh][rr * 2 + 0] + Pr[rr][jh][3].x;
                float iv1 = C[0 + jh][rr * 2 + 1] + Pr[rr][jh][0].y;
                float fv1 = C[2 + jh][rr * 2 + 1] + Pr[rr][jh][1].y;
                float gv1 = C[4 + jh][rr * 2 + 1] + Pr[rr][jh][2].y;
                float ov1 = C[6 + jh][rr * 2 + 1] + Pr[rr][jh][3].y;
                float cn0 = fsigm(fv0) * c[rr][jh * 2 + 0] + fsigm(iv0) * ftanh(gv0);
                float cn1 = fsigm(fv1) * c[rr][jh * 2 + 1] + fsigm(iv1) * ftanh(gv1);
                c[rr][jh * 2 + 0] = cn0;
                c[rr][jh * 2 + 1] = cn1;
                float2 hv;
                hv.x = fsigm(ov0) * ftanh(cn0);
                hv.y = fsigm(ov1) * ftanh(cn1);
                HSo[(size_t)b * 128 + (j >> 1)] = split2(hv);
            }
        }
        // inter-block step barrier: bar -> release-red -> acquire-poll
        __syncthreads();
        if (tid == 0) {
            asm volatile("red.release.gpu.global.add.u32 [%0], %1;"
                         :: "l"(&g_cnt[rd]), "r"(1u) : "memory");
            unsigned target = 8u * (unsigned)(t + 1), v;
            do {
                asm volatile("ld.acquire.gpu.global.u32 %0, [%1];"
                             : "=r"(v) : "l"(&g_cnt[rd]) : "memory");
            } while (v < target);
        }
        __syncthreads();
    }
}

// ---------------- phase 3a: attention logits  [HMMA, double-buffered] -------------
__global__ void k_logits(const float* __restrict__ ba, const float* __restrict__ watt) {
    __shared__ __align__(8) u32 As_s[2][128 * 20];
    __shared__ __align__(8) u32 Bs_s[2][64 * 20];
    int mtile = blockIdx.x, ntile = blockIdx.y, br = blockIdx.z;
    int tid = threadIdx.x;
    int m0 = mtile * 128, n0 = ntile * 64;
    int lane = tid & 31, wid = tid >> 5;
    int g = lane >> 2, tg = lane & 3;
    int wm = wid & 3, wn = wid >> 2;
    int mbase = wm * 32, nbase = wn * 32;
    float C[2][4][4];
#pragma unroll
    for (int mt = 0; mt < 2; mt++)
#pragma unroll
        for (int nt = 0; nt < 4; nt++)
#pragma unroll
            for (int q = 0; q < 4; q++) C[mt][nt][q] = 0.0f;

    // prologue: stage k0 = 0 into buffer 0
    {
#pragma unroll
        for (int i = 0; i < 4; i++) {
            int task = tid + i * 256;
            int m = task >> 3, kp = task & 7;
            int mm = m0 + m;
            *(ull*)&As_s[0][m * 20 + 2 * kp] =
                g_HS2[(((size_t)(2 * br) * SEQ + (mm >> 6)) * BATCH + (mm & 63)) * 128 + kp];
        }
#pragma unroll
        for (int i = 0; i < 2; i++) {
            int task = tid + i * 256;
            int n = task >> 3, kp = task & 7;
            *(ull*)&Bs_s[0][n * 20 + 2 * kp] = g_Wa2[((size_t)br * ADIM + n0 + n) * 256 + kp];
        }
    }
    __syncthreads();

    int buf = 0;
    for (int k0 = 0; k0 < ADIM; k0 += 16) {
        if (k0 + 16 < ADIM) {
            int kn = k0 + 16;
            int rdh = 2 * br + (kn >> 8);
            int kbl = (kn & 255) >> 1;
#pragma unroll
            for (int i = 0; i < 4; i++) {
                int task = tid + i * 256;
                int m = task >> 3, kp = task & 7;
                int mm = m0 + m;
                *(ull*)&As_s[buf ^ 1][m * 20 + 2 * kp] =
                    g_HS2[(((size_t)rdh * SEQ + (mm >> 6)) * BATCH + (mm & 63)) * 128 + kbl + kp];
            }
#pragma unroll
            for (int i = 0; i < 2; i++) {
                int task = tid + i * 256;
                int n = task >> 3, kp = task & 7;
                *(ull*)&Bs_s[buf ^ 1][n * 20 + 2 * kp] =
                    g_Wa2[((size_t)br * ADIM + n0 + n) * 256 + (kn >> 1) + kp];
            }
        }
        const u32* Ac = As_s[buf];
        const u32* Bc = Bs_s[buf];
        u32 Ahi[2][4], Alo[2][4], Bhi[4][2], Blo[4][2];
#pragma unroll
        for (int mt = 0; mt < 2; mt++) {
            int r0 = mbase + mt * 16 + g;
            ull v0 = *(const ull*)&Ac[r0 * 20 + 2 * tg];
            ull v1 = *(const ull*)&Ac[(r0 + 8) * 20 + 2 * tg];
            ull v2 = *(const ull*)&Ac[r0 * 20 + 2 * (tg + 4)];
            ull v3 = *(const ull*)&Ac[(r0 + 8) * 20 + 2 * (tg + 4)];
            Ahi[mt][0] = (u32)v0; Alo[mt][0] = (u32)(v0 >> 32);
            Ahi[mt][1] = (u32)v1; Alo[mt][1] = (u32)(v1 >> 32);
            Ahi[mt][2] = (u32)v2; Alo[mt][2] = (u32)(v2 >> 32);
            Ahi[mt][3] = (u32)v3; Alo[mt][3] = (u32)(v3 >> 32);
        }
#pragma unroll
        for (int nt = 0; nt < 4; nt++) {
            int n = nbase + nt * 8 + g;
            ull v0 = *(const ull*)&Bc[n * 20 + 2 * tg];
            ull v1 = *(const ull*)&Bc[n * 20 + 2 * (tg + 4)];
            Bhi[nt][0] = (u32)v0; Blo[nt][0] = (u32)(v0 >> 32);
            Bhi[nt][1] = (u32)v1; Blo[nt][1] = (u32)(v1 >> 32);
        }
#pragma unroll
        for (int mt = 0; mt < 2; mt++)
#pragma unroll
            for (int nt = 0; nt < 4; nt++) {
                MMA_BF16(C[mt][nt], Ahi[mt], Bhi[nt]);
                MMA_BF16(C[mt][nt], Ahi[mt], Blo[nt]);
                MMA_BF16(C[mt][nt], Alo[mt], Bhi[nt]);
            }
        __syncthreads();
        buf ^= 1;
    }
#pragma unroll
    for (int mt = 0; mt < 2; mt++) {
        float p0 = 0.0f, p1 = 0.0f;
#pragma unroll
        for (int nt = 0; nt < 4; nt++) {
            int nf = n0 + nbase + nt * 8 + 2 * tg;
            float b0 = ba[br * ADIM + nf], w0 = watt[br * ADIM + nf];
            float b1 = ba[br * ADIM + nf + 1], w1 = watt[br * ADIM + nf + 1];
            p0 += ftanh(C[mt][nt][0] + b0) * w0 + ftanh(C[mt][nt][1] + b1) * w1;
            p1 += ftanh(C[mt][nt][2] + b0) * w0 + ftanh(C[mt][nt][3] + b1) * w1;
        }
        p0 += __shfl_xor_sync(0xffffffffu, p0, 1);
        p0 += __shfl_xor_sync(0xffffffffu, p0, 2);
        p1 += __shfl_xor_sync(0xffffffffu, p1, 1);
        p1 += __shfl_xor_sync(0xffffffffu, p1, 2);
        if (tg == 0) {
            int m = m0 + mbase + mt * 16 + g;
            atomicAdd(&g_logit[br][m & 63][m >> 6], p0);
            int m2 = m + 8;
            atomicAdd(&g_logit[br][m2 & 63][m2 >> 6], p1);
        }
    }
}

// ---------------- phase 3b: softmax over S -------------------------------------
__global__ void k_softmax() {
    int br = blockIdx.x >> 6, b = blockIdx.x & 63;
    __shared__ float red[256];
    const float* L = &g_logit[br][b][0];
    int tid = threadIdx.x;
    red[tid] = fmaxf(L[tid], L[tid + 256]); __syncthreads();
    for (int o = 128; o > 0; o >>= 1) { if (tid < o) red[tid] = fmaxf(red[tid], red[tid + o]); __syncthreads(); }
    float mx = red[0]; __syncthreads();
    float e0 = __expf(L[tid] - mx), e1 = __expf(L[tid + 256] - mx);
    red[tid] = e0 + e1; __syncthreads();
    for (int o = 128; o > 0; o >>= 1) { if (tid < o) red[tid] += red[tid + o]; __syncthreads(); }
    float inv = 1.0f / red[0];
    g_attw[br][b][tid] = e0 * inv;
    g_attw[br][b][tid + 256] = e1 * inv;
}

// ---------------- phase 3c: attention-weighted sum (reconstruct h = hi+lo) -------
__global__ void k_attsum() {
    int b = blockIdx.x, br = blockIdx.y;
    int d = threadIdx.x;
    __shared__ float aw[512];
    aw[d] = g_attw[br][b][d];
    __syncthreads();
    int rdh = (d < HDIM) ? (2 * br) : (2 * br + 1);
    int dd = d & 255;
    int kpair = dd >> 1, e = dd & 1;
    const ull* base = g_HS2 + (size_t)rdh * SEQ * BATCH * 128 + (size_t)b * 128 + kpair;
    float a0 = 0.0f, a1 = 0.0f;
    for (int s = 0; s < SEQ; s += 2) {
        ull v0 = base[(size_t)s * BATCH * 128];
        ull v1 = base[(size_t)(s + 1) * BATCH * 128];
        u32 hw0 = (u32)v0, lw0 = (u32)(v0 >> 32);
        u32 hw1 = (u32)v1, lw1 = (u32)(v1 >> 32);
        u32 sh = e ? 0 : 16;
        float h0 = __uint_as_float((hw0 << sh) & 0xffff0000u) + __uint_as_float((lw0 << sh) & 0xffff0000u);
        float h1 = __uint_as_float((hw1 << sh) & 0xffff0000u) + __uint_as_float((lw1 << sh) & 0xffff0000u);
        a0 = fmaf(aw[s],     h0, a0);
        a1 = fmaf(aw[s + 1], h1, a1);
    }
    g_ATT[br][b][d] = a0 + a1;
}

// ---------------- phase 4: routed final FC --------------------------------------
__global__ void k_final(const int* __restrict__ z, const float* __restrict__ Wfc,
                        const float* __restrict__ bfc, float* __restrict__ out) {
    int b = blockIdx.x;
    int tid = threadIdx.x;
    int zb = z[b];
    __shared__ float red0[256], red1[256];
    float a0 = 0.0f, a1 = 0.0f;
    for (int k = tid; k < 1024; k += 256) {
        float v = (k < 512) ? g_ATT[zb + 1][b][k] : g_ATT[0][b][k - 512];
        a0 = fmaf(v, Wfc[k], a0);
        a1 = fmaf(v, Wfc[1024 + k], a1);
    }
    red0[tid] = a0; red1[tid] = a1; __syncthreads();
    for (int o = 128; o > 0; o >>= 1) {
        if (tid < o) { red0[tid] += red0[tid + o]; red1[tid] += red1[tid + o]; }
        __syncthreads();
    }
    if (tid == 0) {
        out[b * 2 + 0] = red0[0] + bfc[0];
        out[b * 2 + 1] = red1[0] + bfc[1];
    }
}

// ---------------- copy general + specifics into d_out ---------------------------
__global__ void k_copyout(float* __restrict__ out) {
    int idx = blockIdx.x * blockDim.x + threadIdx.x;
    if (idx < NBR * BATCH * ADIM) out[128 + idx] = (&g_ATT[0][0][0])[idx];
}

// ---------------- launcher -------------------------------------------------------
extern "C" void kernel_launch(void* const* d_in, const int* in_sizes, int n_in,
                              void* d_out, int out_size) {
    const int*   x     = (const int*)  d_in[0];
    const int*   z     = (const int*)  d_in[1];
    const float* emb   = (const float*)d_in[2];
    const float* Wih_f = (const float*)d_in[3];
    const float* Whh_f = (const float*)d_in[4];
    const float* bih_f = (const float*)d_in[5];
    const float* bhh_f = (const float*)d_in[6];
    const float* Wih_b = (const float*)d_in[7];
    const float* Whh_b = (const float*)d_in[8];
    const float* bih_b = (const float*)d_in[9];
    const float* bhh_b = (const float*)d_in[10];
    const float* Wa    = (const float*)d_in[11];
    const float* ba    = (const float*)d_in[12];
    const float* watt  = (const float*)d_in[13];
    const float* Wfc   = (const float*)d_in[14];
    const float* bfc   = (const float*)d_in[15];
    float* out = (float*)d_out;

    cudaFuncSetAttribute(k_scan, cudaFuncAttributeMaxDynamicSharedMemorySize, SCAN_SMEM);

    k_init<<<1280, 256>>>();
    k_presplit_emb<<<(VOCAB * EKP + 255) / 256, 256>>>(emb);
    k_presplit_wih<<<(NRD * GDIM * EKP + 255) / 256, 256>>>(Wih_f, Wih_b);
    k_presplit_wa<<<(NBR * ADIM * 256 + 255) / 256, 256>>>(Wa);
    k_inputproj<<<dim3(256, 16, 10), 256>>>(x, bih_f, bhh_f, bih_b, bhh_b);
    k_scan<<<80, 256, SCAN_SMEM>>>(Whh_f, Whh_b);
    k_logits<<<dim3(256, 8, 5), 256>>>(ba, watt);
    k_softmax<<<320, 256>>>();
    k_attsum<<<dim3(64, 5), 512>>>();
    k_final<<<64, 256>>>(z, Wfc, bfc, out);
    k_copyout<<<640, 256>>>(out);
}

// round 15
// speedup vs baseline: 1.2539x; 1.0227x over previous
#include <cuda_runtime.h>
#include <cuda_bf16.h>

#define HDIM   256
#define GDIM   1024      // 4*H
#define BATCH  64
#define SEQ    512
#define NRD    10        // 5 branches * 2 directions
#define NBR    5
#define EDIM   300
#define ADIM   512       // 2*H
#define VOCAB  50000
#define EKP    152       // padded kpair count for EDIM=300 (150 real + 2 zero)

typedef unsigned long long ull;
typedef unsigned int u32;

// ---------------- scratch (device globals; no allocation allowed) ----------------
__device__ float g_P  [335544320];               // [NRD][SEQ][BATCH][GDIM]
__device__ ull   g_HS2[41943040];                // [NRD][SEQ][BATCH][128]  h pre-split
__device__ ull   g_E2 [VOCAB * EKP];             // emb pre-split
__device__ ull   g_W2 [NRD * GDIM * EKP];        // Wih pre-split
__device__ ull   g_Wa2[NBR * ADIM * 256];        // Wa pre-split
__device__ float g_ATT[NBR][BATCH][ADIM];
__device__ float g_logit[NBR][BATCH][SEQ];
__device__ float g_attw [NBR][BATCH][SEQ];
__device__ unsigned g_cnt[NRD];

__device__ __forceinline__ float fsigm(float x) { return 1.0f / (1.0f + __expf(-x)); }
__device__ __forceinline__ float ftanh(float x) { return 1.0f - 2.0f / (__expf(2.0f * x) + 1.0f); }

// bf16 2-term split of a float pair -> (hi word | lo word << 32)
__device__ __forceinline__ ull split2(float2 v) {
    __nv_bfloat162 h = __floats2bfloat162_rn(v.x, v.y);
    float r0 = v.x - __bfloat162float(h.x);
    float r1 = v.y - __bfloat162float(h.y);
    __nv_bfloat162 l = __floats2bfloat162_rn(r0, r1);
    u32 hw = *(u32*)&h;
    u32 lw = *(u32*)&l;
    return (ull)hw | ((ull)lw << 32);
}

#define MMA_BF16(c, a, b) \
    asm volatile("mma.sync.aligned.m16n8k16.row.col.f32.bf16.bf16.f32 " \
                 "{%0,%1,%2,%3}, {%4,%5,%6,%7}, {%8,%9}, {%0,%1,%2,%3};" \
                 : "+f"((c)[0]), "+f"((c)[1]), "+f"((c)[2]), "+f"((c)[3]) \
                 : "r"((a)[0]), "r"((a)[1]), "r"((a)[2]), "r"((a)[3]), \
                   "r"((b)[0]), "r"((b)[1]))

// ---------------- init -----------------------------------------------------------
__global__ void k_init() {
    int idx = blockIdx.x * blockDim.x + threadIdx.x;
    if (idx < NBR * BATCH * SEQ) ((float*)g_logit)[idx] = 0.0f;
    if (idx < NRD)               g_cnt[idx] = 0u;
}

// ---------------- pre-split tables ------------------------------------------------
__global__ void k_presplit_emb(const float* __restrict__ emb) {
    long long idx = (long long)blockIdx.x * blockDim.x + threadIdx.x;
    if (idx >= (long long)VOCAB * EKP) return;
    int row = (int)(idx / EKP), kp = (int)(idx % EKP);
    float2 v = (kp < 150) ? *(const float2*)(emb + (size_t)row * EDIM + 2 * kp)
                          : make_float2(0.0f, 0.0f);
    g_E2[idx] = split2(v);
}
__global__ void k_presplit_wih(const float* __restrict__ Wih_f, const float* __restrict__ Wih_b) {
    long long idx = (long long)blockIdx.x * blockDim.x + threadIdx.x;
    if (idx >= (long long)NRD * GDIM * EKP) return;
    int kp = (int)(idx % EKP);
    int row = (int)((idx / EKP) % GDIM);
    int rd = (int)(idx / ((long long)GDIM * EKP));
    int branch = rd >> 1, dir = rd & 1;
    const float* W = (dir ? Wih_b : Wih_f) + (size_t)branch * GDIM * EDIM;
    float2 v = (kp < 150) ? *(const float2*)(W + (size_t)row * EDIM + 2 * kp)
                          : make_float2(0.0f, 0.0f);
    g_W2[idx] = split2(v);
}
__global__ void k_presplit_wa(const float* __restrict__ Wa) {
    long long idx = (long long)blockIdx.x * blockDim.x + threadIdx.x;
    if (idx >= (long long)NBR * ADIM * 256) return;
    g_Wa2[idx] = split2(*(const float2*)(Wa + 2 * idx));
}

// ---------------- phase 1: P = emb[x] @ Wih.T + bias  [HMMA, double-buffered] -----
__global__ void k_inputproj(const int* __restrict__ x,
                            const float* __restrict__ bih_f, const float* __restrict__ bhh_f,
                            const float* __restrict__ bih_b, const float* __restrict__ bhh_b) {
    __shared__ __align__(8) u32 As_s[2][128 * 20];
    __shared__ __align__(8) u32 Bs_s[2][64 * 20];
    __shared__ int tok[128];
    int mtile = blockIdx.x, ntile = blockIdx.y, rd = blockIdx.z;
    int branch = rd >> 1, dir = rd & 1;
    const float* bi  = (dir ? bih_b : bih_f) + branch * GDIM;
    const float* bh  = (dir ? bhh_b : bhh_f) + branch * GDIM;
    int tid = threadIdx.x;
    int m0 = mtile * 128, n0 = ntile * 64;
    if (tid < 128) {
        int m = m0 + tid;
        tok[tid] = x[(m & 63) * SEQ + (m >> 6)];
    }
    int lane = tid & 31, wid = tid >> 5;
    int g = lane >> 2, tg = lane & 3;
    int wm = wid & 3, wn = wid >> 2;
    int mbase = wm * 32, nbase = wn * 32;
    float C[2][4][4];
#pragma unroll
    for (int mt = 0; mt < 2; mt++)
#pragma unroll
        for (int nt = 0; nt < 4; nt++)
#pragma unroll
            for (int q = 0; q < 4; q++) C[mt][nt][q] = 0.0f;
    __syncthreads();

    {
#pragma unroll
        for (int i = 0; i < 4; i++) {
            int task = tid + i * 256;
            int m = task >> 3, kp = task & 7;
            *(ull*)&As_s[0][m * 20 + 2 * kp] = g_E2[(size_t)tok[m] * EKP + kp];
        }
#pragma unroll
        for (int i = 0; i < 2; i++) {
            int task = tid + i * 256;
            int n = task >> 3, kp = task & 7;
            *(ull*)&Bs_s[0][n * 20 + 2 * kp] = g_W2[((size_t)rd * GDIM + n0 + n) * EKP + kp];
        }
    }
    __syncthreads();

    int buf = 0;
    for (int k0 = 0; k0 < 304; k0 += 16) {
        if (k0 + 16 < 304) {
            int kb = (k0 + 16) >> 1;
#pragma unroll
            for (int i = 0; i < 4; i++) {
                int task = tid + i * 256;
                int m = task >> 3, kp = task & 7;
                *(ull*)&As_s[buf ^ 1][m * 20 + 2 * kp] = g_E2[(size_t)tok[m] * EKP + kb + kp];
            }
#pragma unroll
            for (int i = 0; i < 2; i++) {
                int task = tid + i * 256;
                int n = task >> 3, kp = task & 7;
                *(ull*)&Bs_s[buf ^ 1][n * 20 + 2 * kp] = g_W2[((size_t)rd * GDIM + n0 + n) * EKP + kb + kp];
            }
        }
        const u32* Ac = As_s[buf];
        const u32* Bc = Bs_s[buf];
        u32 Ahi[2][4], Alo[2][4], Bhi[4][2], Blo[4][2];
#pragma unroll
        for (int mt = 0; mt < 2; mt++) {
            int r0 = mbase + mt * 16 + g;
            ull v0 = *(const ull*)&Ac[r0 * 20 + 2 * tg];
            ull v1 = *(const ull*)&Ac[(r0 + 8) * 20 + 2 * tg];
            ull v2 = *(const ull*)&Ac[r0 * 20 + 2 * (tg + 4)];
            ull v3 = *(const ull*)&Ac[(r0 + 8) * 20 + 2 * (tg + 4)];
            Ahi[mt][0] = (u32)v0; Alo[mt][0] = (u32)(v0 >> 32);
            Ahi[mt][1] = (u32)v1; Alo[mt][1] = (u32)(v1 >> 32);
            Ahi[mt][2] = (u32)v2; Alo[mt][2] = (u32)(v2 >> 32);
            Ahi[mt][3] = (u32)v3; Alo[mt][3] = (u32)(v3 >> 32);
        }
#pragma unroll
        for (int nt = 0; nt < 4; nt++) {
            int n = nbase + nt * 8 + g;
            ull v0 = *(const ull*)&Bc[n * 20 + 2 * tg];
            ull v1 = *(const ull*)&Bc[n * 20 + 2 * (tg + 4)];
            Bhi[nt][0] = (u32)v0; Blo[nt][0] = (u32)(v0 >> 32);
            Bhi[nt][1] = (u32)v1; Blo[nt][1] = (u32)(v1 >> 32);
        }
#pragma unroll
        for (int mt = 0; mt < 2; mt++)
#pragma unroll
            for (int nt = 0; nt < 4; nt++) {
                MMA_BF16(C[mt][nt], Ahi[mt], Bhi[nt]);
                MMA_BF16(C[mt][nt], Ahi[mt], Blo[nt]);
                MMA_BF16(C[mt][nt], Alo[mt], Bhi[nt]);
            }
        __syncthreads();
        buf ^= 1;
    }
#pragma unroll
    for (int mt = 0; mt < 2; mt++)
#pragma unroll
        for (int rr = 0; rr < 2; rr++) {
            int m = m0 + mbase + mt * 16 + g + rr * 8;
            float* Pp = g_P + (((size_t)rd * SEQ + (m >> 6)) * BATCH + (m & 63)) * GDIM + n0 + nbase;
#pragma unroll
            for (int nt = 0; nt < 4; nt++) {
                int nl = nt * 8 + 2 * tg;
                int nf = n0 + nbase + nl;
                float2 o;
                o.x = C[mt][nt][rr * 2 + 0] + bi[nf] + bh[nf];
                o.y = C[mt][nt][rr * 2 + 1] + bi[nf + 1] + bh[nf + 1];
                *(float2*)(Pp + nl) = o;
            }
        }
}

// ---------------- phase 2: persistent recurrent scan  [bf16-split HMMA] -----------
// 80 blocks = 10 recs x 8 j-slices; launched as 10 clusters of 8 when supported.
// Step barrier: barrier.cluster (release/acquire) replaces L2-atomic spin.
#define A_CHUNK 1032            // words/chunk: 64 rows * 16 + 8 pad
#define B_CHUNK 2056            // words/chunk: 128 rows * 16 + 8 pad
#define SCAN_SMEM ((16 * A_CHUNK + 16 * B_CHUNK) * 4)   // 197,632 B

__global__ void __launch_bounds__(256, 1)
k_scan(const float* __restrict__ Whh_f, const float* __restrict__ Whh_b, int use_cluster) {
    extern __shared__ __align__(16) u32 smw[];
    u32* Bw = smw;                     // Whh split, resident
    u32* Aw = smw + 16 * B_CHUNK;      // h split, restaged per step

    int rd = blockIdx.x >> 3;
    int blk = blockIdx.x & 7;
    int j0 = blk * 32;
    int branch = rd >> 1, dir = rd & 1;
    const float* W = (dir ? Whh_b : Whh_f) + (size_t)branch * GDIM * HDIM;
    int tid = threadIdx.x;
    int lane = tid & 31, wid = tid >> 5;
    int g = lane >> 2, tg = lane & 3;
    int wm = wid & 3, wn = wid >> 2;
    int mbase = wm * 16, nbase = wn * 64;
    int xg = g << 1;                   // xor swizzle key (rows ≡ g mod 8)

    // ---- stage Whh slice (permuted rows, bf16 split), one time ----
    for (int p = tid; p < 128 * 128; p += 256) {
        int r = p >> 7;                 // n' 0..127
        int kpair = p & 127;
        int wnn = r >> 6, w = r & 63;
        int gate = w >> 4, jl = wnn * 16 + (w & 15);
        float2 v = *(const float2*)&W[(size_t)(gate * HDIM + j0 + jl) * HDIM + 2 * kpair];
        int idx = (kpair >> 3) * B_CHUNK + r * 16 + ((2 * (kpair & 7)) ^ ((r & 7) << 1));
        *(ull*)&Bw[idx] = split2(v);
    }
    float c[2][4];                      // [rr][jh*2+q]
#pragma unroll
    for (int a = 0; a < 2; a++)
#pragma unroll
        for (int b = 0; b < 4; b++) c[a][b] = 0.0f;
    __syncthreads();

    for (int t = 0; t < SEQ; ++t) {
        int sidx = dir ? (SEQ - 1 - t) : t;
        // prefetch P preacts for this thread's 32 output units
        const float* Pb = g_P + ((size_t)rd * SEQ + sidx) * BATCH * GDIM;
        float2 Pr[2][2][4];             // [rr][jh][gate]
#pragma unroll
        for (int rr = 0; rr < 2; rr++) {
            int b = mbase + g + 8 * rr;
#pragma unroll
            for (int jh = 0; jh < 2; jh++) {
                int j = j0 + wn * 16 + jh * 8 + 2 * tg;
#pragma unroll
                for (int gate = 0; gate < 4; gate++)
                    Pr[rr][jh][gate] = *(const float2*)&Pb[(size_t)b * GDIM + gate * HDIM + j];
            }
        }

        // stage h(t-1) from g_HS2[sidx_prev] (zeros at t==0)
        if (t == 0) {
#pragma unroll
            for (int i = 0; i < 32; i++) {
                int p = tid + i * 256;
                int b = p >> 7, kpair = p & 127;
                int idx = (kpair >> 3) * A_CHUNK + b * 16 + ((2 * (kpair & 7)) ^ ((b & 7) << 1));
                *(ull*)&Aw[idx] = 0ull;
            }
        } else {
            int sidx_prev = dir ? (SEQ - t) : (t - 1);
            const ull* Hs = g_HS2 + ((size_t)rd * SEQ + sidx_prev) * BATCH * 128;
#pragma unroll
            for (int i = 0; i < 32; i++) {
                int p = tid + i * 256;
                int b = p >> 7, kpair = p & 127;
                ull v = __ldcv(&Hs[b * 128 + kpair]);
                int idx = (kpair >> 3) * A_CHUNK + b * 16 + ((2 * (kpair & 7)) ^ ((b & 7) << 1));
                *(ull*)&Aw[idx] = v;
            }
        }
        __syncthreads();

        float C[8][4];
#pragma unroll
        for (int nt = 0; nt < 8; nt++)
#pragma unroll
            for (int q = 0; q < 4; q++) C[nt][q] = 0.0f;

#pragma unroll 4
        for (int chunk = 0; chunk < 16; chunk++) {
            const u32* Ac = Aw + chunk * A_CHUNK;
            const u32* Bc = Bw + chunk * B_CHUNK;
            u32 Ahi[4], Alo[4];
            {
                int r0 = mbase + g;
                ull v0 = *(const ull*)&Ac[r0 * 16 + ((2 * tg) ^ xg)];
                ull v1 = *(const ull*)&Ac[(r0 + 8) * 16 + ((2 * tg) ^ xg)];
                ull v2 = *(const ull*)&Ac[r0 * 16 + ((2 * (tg + 4)) ^ xg)];
                ull v3 = *(const ull*)&Ac[(r0 + 8) * 16 + ((2 * (tg + 4)) ^ xg)];
                Ahi[0] = (u32)v0; Alo[0] = (u32)(v0 >> 32);
                Ahi[1] = (u32)v1; Alo[1] = (u32)(v1 >> 32);
                Ahi[2] = (u32)v2; Alo[2] = (u32)(v2 >> 32);
                Ahi[3] = (u32)v3; Alo[3] = (u32)(v3 >> 32);
            }
#pragma unroll
            for (int nt = 0; nt < 8; nt++) {
                int n = nbase + nt * 8 + g;
                ull v0 = *(const ull*)&Bc[n * 16 + ((2 * tg) ^ xg)];
                ull v1 = *(const ull*)&Bc[n * 16 + ((2 * (tg + 4)) ^ xg)];
                u32 Bhi[2], Blo[2];
                Bhi[0] = (u32)v0; Blo[0] = (u32)(v0 >> 32);
                Bhi[1] = (u32)v1; Blo[1] = (u32)(v1 >> 32);
                MMA_BF16(C[nt], Ahi, Bhi);
                MMA_BF16(C[nt], Ahi, Blo);
                MMA_BF16(C[nt], Alo, Bhi);
            }
        }

        // epilogue: gates + cell update; h stored pre-split to g_HS2
        ull* HSo = g_HS2 + ((size_t)rd * SEQ + sidx) * BATCH * 128;
#pragma unroll
        for (int rr = 0; rr < 2; rr++) {
            int b = mbase + g + 8 * rr;
#pragma unroll
            for (int jh = 0; jh < 2; jh++) {
                int j = j0 + wn * 16 + jh * 8 + 2 * tg;
                float iv0 = C[0 + jh][rr * 2 + 0] + Pr[rr][jh][0].x;
                float fv0 = C[2 + jh][rr * 2 + 0] + Pr[rr][jh][1].x;
                float gv0 = C[4 + jh][rr * 2 + 0] + Pr[rr][jh][2].x;
                float ov0 = C[6 + jh][rr * 2 + 0] + Pr[rr][jh][3].x;
                float iv1 = C[0 + jh][rr * 2 + 1] + Pr[rr][jh][0].y;
                float fv1 = C[2 + jh][rr * 2 + 1] + Pr[rr][jh][1].y;
                float gv1 = C[4 + jh][rr * 2 + 1] + Pr[rr][jh][2].y;
                float ov1 = C[6 + jh][rr * 2 + 1] + Pr[rr][jh][3].y;
                float cn0 = fsigm(fv0) * c[rr][jh * 2 + 0] + fsigm(iv0) * ftanh(gv0);
                float cn1 = fsigm(fv1) * c[rr][jh * 2 + 1] + fsigm(iv1) * ftanh(gv1);
                c[rr][jh * 2 + 0] = cn0;
                c[rr][jh * 2 + 1] = cn1;
                float2 hv;
                hv.x = fsigm(ov0) * ftanh(cn0);
                hv.y = fsigm(ov1) * ftanh(cn1);
                HSo[(size_t)b * 128 + (j >> 1)] = split2(hv);
            }
        }
        // inter-block step barrier
        if (use_cluster) {
            // release/acquire cluster barrier: orders the h stores, syncs all 8 CTAs,
            // and doubles as the block-wide barrier protecting Aw reuse.
            asm volatile("barrier.cluster.arrive.aligned;" ::: "memory");
            asm volatile("barrier.cluster.wait.aligned;" ::: "memory");
        } else {
            __syncthreads();
            if (tid == 0) {
                asm volatile("red.release.gpu.global.add.u32 [%0], %1;"
                             :: "l"(&g_cnt[rd]), "r"(1u) : "memory");
                unsigned target = 8u * (unsigned)(t + 1), v;
                do {
                    asm volatile("ld.acquire.gpu.global.u32 %0, [%1];"
                                 : "=r"(v) : "l"(&g_cnt[rd]) : "memory");
                } while (v < target);
            }
            __syncthreads();
        }
    }
}

// ---------------- phase 3a: attention logits  [HMMA, double-buffered] -------------
__global__ void k_logits(const float* __restrict__ ba, const float* __restrict__ watt) {
    __shared__ __align__(8) u32 As_s[2][128 * 20];
    __shared__ __align__(8) u32 Bs_s[2][64 * 20];
    int mtile = blockIdx.x, ntile = blockIdx.y, br = blockIdx.z;
    int tid = threadIdx.x;
    int m0 = mtile * 128, n0 = ntile * 64;
    int lane = tid & 31, wid = tid >> 5;
    int g = lane >> 2, tg = lane & 3;
    int wm = wid & 3, wn = wid >> 2;
    int mbase = wm * 32, nbase = wn * 32;
    float C[2][4][4];
#pragma unroll
    for (int mt = 0; mt < 2; mt++)
#pragma unroll
        for (int nt = 0; nt < 4; nt++)
#pragma unroll
            for (int q = 0; q < 4; q++) C[mt][nt][q] = 0.0f;

    {
#pragma unroll
        for (int i = 0; i < 4; i++) {
            int task = tid + i * 256;
            int m = task >> 3, kp = task & 7;
            int mm = m0 + m;
            *(ull*)&As_s[0][m * 20 + 2 * kp] =
                g_HS2[(((size_t)(2 * br) * SEQ + (mm >> 6)) * BATCH + (mm & 63)) * 128 + kp];
        }
#pragma unroll
        for (int i = 0; i < 2; i++) {
            int task = tid + i * 256;
            int n = task >> 3, kp = task & 7;
            *(ull*)&Bs_s[0][n * 20 + 2 * kp] = g_Wa2[((size_t)br * ADIM + n0 + n) * 256 + kp];
        }
    }
    __syncthreads();

    int buf = 0;
    for (int k0 = 0; k0 < ADIM; k0 += 16) {
        if (k0 + 16 < ADIM) {
            int kn = k0 + 16;
            int rdh = 2 * br + (kn >> 8);
            int kbl = (kn & 255) >> 1;
#pragma unroll
            for (int i = 0; i < 4; i++) {
                int task = tid + i * 256;
                int m = task >> 3, kp = task & 7;
                int mm = m0 + m;
                *(ull*)&As_s[buf ^ 1][m * 20 + 2 * kp] =
                    g_HS2[(((size_t)rdh * SEQ + (mm >> 6)) * BATCH + (mm & 63)) * 128 + kbl + kp];
            }
#pragma unroll
            for (int i = 0; i < 2; i++) {
                int task = tid + i * 256;
                int n = task >> 3, kp = task & 7;
                *(ull*)&Bs_s[buf ^ 1][n * 20 + 2 * kp] =
                    g_Wa2[((size_t)br * ADIM + n0 + n) * 256 + (kn >> 1) + kp];
            }
        }
        const u32* Ac = As_s[buf];
        const u32* Bc = Bs_s[buf];
        u32 Ahi[2][4], Alo[2][4], Bhi[4][2], Blo[4][2];
#pragma unroll
        for (int mt = 0; mt < 2; mt++) {
            int r0 = mbase + mt * 16 + g;
            ull v0 = *(const ull*)&Ac[r0 * 20 + 2 * tg];
            ull v1 = *(const ull*)&Ac[(r0 + 8) * 20 + 2 * tg];
            ull v2 = *(const ull*)&Ac[r0 * 20 + 2 * (tg + 4)];
            ull v3 = *(const ull*)&Ac[(r0 + 8) * 20 + 2 * (tg + 4)];
            Ahi[mt][0] = (u32)v0; Alo[mt][0] = (u32)(v0 >> 32);
            Ahi[mt][1] = (u32)v1; Alo[mt][1] = (u32)(v1 >> 32);
            Ahi[mt][2] = (u32)v2; Alo[mt][2] = (u32)(v2 >> 32);
            Ahi[mt][3] = (u32)v3; Alo[mt][3] = (u32)(v3 >> 32);
        }
#pragma unroll
        for (int nt = 0; nt < 4; nt++) {
            int n = nbase + nt * 8 + g;
            ull v0 = *(const ull*)&Bc[n * 20 + 2 * tg];
            ull v1 = *(const ull*)&Bc[n * 20 + 2 * (tg + 4)];
            Bhi[nt][0] = (u32)v0; Blo[nt][0] = (u32)(v0 >> 32);
            Bhi[nt][1] = (u32)v1; Blo[nt][1] = (u32)(v1 >> 32);
        }
#pragma unroll
        for (int mt = 0; mt < 2; mt++)
#pragma unroll
            for (int nt = 0; nt < 4; nt++) {
                MMA_BF16(C[mt][nt], Ahi[mt], Bhi[nt]);
                MMA_BF16(C[mt][nt], Ahi[mt], Blo[nt]);
                MMA_BF16(C[mt][nt], Alo[mt], Bhi[nt]);
            }
        __syncthreads();
        buf ^= 1;
    }
#pragma unroll
    for (int mt = 0; mt < 2; mt++) {
        float p0 = 0.0f, p1 = 0.0f;
#pragma unroll
        for (int nt = 0; nt < 4; nt++) {
            int nf = n0 + nbase + nt * 8 + 2 * tg;
            float b0 = ba[br * ADIM + nf], w0 = watt[br * ADIM + nf];
            float b1 = ba[br * ADIM + nf + 1], w1 = watt[br * ADIM + nf + 1];
            p0 += ftanh(C[mt][nt][0] + b0) * w0 + ftanh(C[mt][nt][1] + b1) * w1;
            p1 += ftanh(C[mt][nt][2] + b0) * w0 + ftanh(C[mt][nt][3] + b1) * w1;
        }
        p0 += __shfl_xor_sync(0xffffffffu, p0, 1);
        p0 += __shfl_xor_sync(0xffffffffu, p0, 2);
        p1 += __shfl_xor_sync(0xffffffffu, p1, 1);
        p1 += __shfl_xor_sync(0xffffffffu, p1, 2);
        if (tg == 0) {
            int m = m0 + mbase + mt * 16 + g;
            atomicAdd(&g_logit[br][m & 63][m >> 6], p0);
            int m2 = m + 8;
            atomicAdd(&g_logit[br][m2 & 63][m2 >> 6], p1);
        }
    }
}

// ---------------- phase 3b: softmax over S -------------------------------------
__global__ void k_softmax() {
    int br = blockIdx.x >> 6, b = blockIdx.x & 63;
    __shared__ float red[256];
    const float* L = &g_logit[br][b][0];
    int tid = threadIdx.x;
    red[tid] = fmaxf(L[tid], L[tid + 256]); __syncthreads();
    for (int o = 128; o > 0; o >>= 1) { if (tid < o) red[tid] = fmaxf(red[tid], red[tid + o]); __syncthreads(); }
    float mx = red[0]; __syncthreads();
    float e0 = __expf(L[tid] - mx), e1 = __expf(L[tid + 256] - mx);
    red[tid] = e0 + e1; __syncthreads();
    for (int o = 128; o > 0; o >>= 1) { if (tid < o) red[tid] += red[tid + o]; __syncthreads(); }
    float inv = 1.0f / red[0];
    g_attw[br][b][tid] = e0 * inv;
    g_attw[br][b][tid + 256] = e1 * inv;
}

// ---------------- phase 3c: attention-weighted sum (reconstruct h = hi+lo) -------
__global__ void k_attsum() {
    int b = blockIdx.x, br = blockIdx.y;
    int d = threadIdx.x;
    __shared__ float aw[512];
    aw[d] = g_attw[br][b][d];
    __syncthreads();
    int rdh = (d < HDIM) ? (2 * br) : (2 * br + 1);
    int dd = d & 255;
    int kpair = dd >> 1, e = dd & 1;
    const ull* base = g_HS2 + (size_t)rdh * SEQ * BATCH * 128 + (size_t)b * 128 + kpair;
    float a0 = 0.0f, a1 = 0.0f;
    for (int s = 0; s < SEQ; s += 2) {
        ull v0 = base[(size_t)s * BATCH * 128];
        ull v1 = base[(size_t)(s + 1) * BATCH * 128];
        u32 hw0 = (u32)v0, lw0 = (u32)(v0 >> 32);
        u32 hw1 = (u32)v1, lw1 = (u32)(v1 >> 32);
        u32 sh = e ? 0 : 16;
        float h0 = __uint_as_float((hw0 << sh) & 0xffff0000u) + __uint_as_float((lw0 << sh) & 0xffff0000u);
        float h1 = __uint_as_float((hw1 << sh) & 0xffff0000u) + __uint_as_float((lw1 << sh) & 0xffff0000u);
        a0 = fmaf(aw[s],     h0, a0);
        a1 = fmaf(aw[s + 1], h1, a1);
    }
    g_ATT[br][b][d] = a0 + a1;
}

// ---------------- phase 4: routed final FC --------------------------------------
__global__ void k_final(const int* __restrict__ z, const float* __restrict__ Wfc,
                        const float* __restrict__ bfc, float* __restrict__ out) {
    int b = blockIdx.x;
    int tid = threadIdx.x;
    int zb = z[b];
    __shared__ float red0[256], red1[256];
    float a0 = 0.0f, a1 = 0.0f;
    for (int k = tid; k < 1024; k += 256) {
        float v = (k < 512) ? g_ATT[zb + 1][b][k] : g_ATT[0][b][k - 512];
        a0 = fmaf(v, Wfc[k], a0);
        a1 = fmaf(v, Wfc[1024 + k], a1);
    }
    red0[tid] = a0; red1[tid] = a1; __syncthreads();
    for (int o = 128; o > 0; o >>= 1) {
        if (tid < o) { red0[tid] += red0[tid + o]; red1[tid] += red1[tid + o]; }
        __syncthreads();
    }
    if (tid == 0) {
        out[b * 2 + 0] = red0[0] + bfc[0];
        out[b * 2 + 1] = red1[0] + bfc[1];
    }
}

// ---------------- copy general + specifics into d_out ---------------------------
__global__ void k_copyout(float* __restrict__ out) {
    int idx = blockIdx.x * blockDim.x + threadIdx.x;
    if (idx < NBR * BATCH * ADIM) out[128 + idx] = (&g_ATT[0][0][0])[idx];
}

// ---------------- launcher -------------------------------------------------------
extern "C" void kernel_launch(void* const* d_in, const int* in_sizes, int n_in,
                              void* d_out, int out_size) {
    const int*   x     = (const int*)  d_in[0];
    const int*   z     = (const int*)  d_in[1];
    const float* emb   = (const float*)d_in[2];
    const float* Wih_f = (const float*)d_in[3];
    const float* Whh_f = (const float*)d_in[4];
    const float* bih_f = (const float*)d_in[5];
    const float* bhh_f = (const float*)d_in[6];
    const float* Wih_b = (const float*)d_in[7];
    const float* Whh_b = (const float*)d_in[8];
    const float* bih_b = (const float*)d_in[9];
    const float* bhh_b = (const float*)d_in[10];
    const float* Wa    = (const float*)d_in[11];
    const float* ba    = (const float*)d_in[12];
    const float* watt  = (const float*)d_in[13];
    const float* Wfc   = (const float*)d_in[14];
    const float* bfc   = (const float*)d_in[15];
    float* out = (float*)d_out;

    cudaFuncSetAttribute(k_scan, cudaFuncAttributeMaxDynamicSharedMemorySize, SCAN_SMEM);

    k_init<<<1280, 256>>>();
    k_presplit_emb<<<(VOCAB * EKP + 255) / 256, 256>>>(emb);
    k_presplit_wih<<<(NRD * GDIM * EKP + 255) / 256, 256>>>(Wih_f, Wih_b);
    k_presplit_wa<<<(NBR * ADIM * 256 + 255) / 256, 256>>>(Wa);
    k_inputproj<<<dim3(256, 16, 10), 256>>>(x, bih_f, bhh_f, bih_b, bhh_b);

    // scan: try cluster launch (10 clusters of 8); fall back to atomic barrier
    {
        cudaLaunchConfig_t cfg = {};
        cfg.gridDim = dim3(80, 1, 1);
        cfg.blockDim = dim3(256, 1, 1);
        cfg.dynamicSmemBytes = SCAN_SMEM;
        cudaLaunchAttribute attrs[1];
        attrs[0].id = cudaLaunchAttributeClusterDimension;
        attrs[0].val.clusterDim = {8, 1, 1};
        cfg.attrs = attrs;
        cfg.numAttrs = 1;
        cudaError_t err = cudaLaunchKernelEx(&cfg, k_scan, Whh_f, Whh_b, 1);
        if (err != cudaSuccess) {
            (void)cudaGetLastError();   // clear
            k_scan<<<80, 256, SCAN_SMEM>>>(Whh_f, Whh_b, 0);
        }
    }

    k_logits<<<dim3(256, 8, 5), 256>>>(ba, watt);
    k_softmax<<<320, 256>>>();
    k_attsum<<<dim3(64, 5), 512>>>();
    k_final<<<64, 256>>>(z, Wfc, bfc, out);
    k_copyout<<<640, 256>>>(out);
}

// round 17
// speedup vs baseline: 1.5350x; 1.2242x over previous
#include <cuda_runtime.h>
#include <cuda_fp16.h>
#include <cuda_bf16.h>

#define HDIM   256
#define GDIM   1024      // 4*H
#define BATCH  64
#define SEQ    512
#define NRD    10        // 5 branches * 2 directions
#define NBR    5
#define EDIM   300
#define ADIM   512       // 2*H
#define VOCAB  50000
#define EKP    152       // padded kpair count for EDIM=300 (150 real + 2 zero)
#define WSCALE 16.0f
#define INVWS  0.0625f

typedef unsigned long long ull;
typedef unsigned int u32;

// ---------------- scratch (device globals; no allocation allowed) ----------------
__device__ float g_P  [335544320];               // [NRD][SEQ][BATCH][GDIM]
__device__ ull   g_HS2[41943040];                // [NRD][SEQ][BATCH][128]  h fp16-split
__device__ ull   g_E2 [VOCAB * EKP];             // emb fp16-split (scale 1)
__device__ ull   g_W2 [NRD * GDIM * EKP];        // Wih fp16-split (scale 16)
__device__ ull   g_Wa2[NBR * ADIM * 256];        // Wa fp16-split (scale 16)
__device__ float g_ATT[NBR][BATCH][ADIM];
__device__ float g_logit[NBR][BATCH][SEQ];
__device__ float g_attw [NBR][BATCH][SEQ];
__device__ unsigned g_cnt[NRD];

__device__ __forceinline__ float fsigm(float x) { return 1.0f / (1.0f + __expf(-x)); }
__device__ __forceinline__ float ftanh(float x) { return 1.0f - 2.0f / (__expf(2.0f * x) + 1.0f); }

// fp16 2-term split of a scaled float pair -> (hi half2 | lo half2 << 32)
__device__ __forceinline__ ull split2h(float2 v, float s) {
    v.x *= s; v.y *= s;
    __half2 h = __floats2half2_rn(v.x, v.y);
    float r0 = v.x - __half2float(__low2half(h));
    float r1 = v.y - __half2float(__high2half(h));
    __half2 l = __floats2half2_rn(r0, r1);
    u32 hw = *(u32*)&h;
    u32 lw = *(u32*)&l;
    return (ull)hw | ((ull)lw << 32);
}

#define MMA_F16(c, a, b) \
    asm volatile("mma.sync.aligned.m16n8k16.row.col.f32.f16.f16.f32 " \
                 "{%0,%1,%2,%3}, {%4,%5,%6,%7}, {%8,%9}, {%0,%1,%2,%3};" \
                 : "+f"((c)[0]), "+f"((c)[1]), "+f"((c)[2]), "+f"((c)[3]) \
                 : "r"((a)[0]), "r"((a)[1]), "r"((a)[2]), "r"((a)[3]), \
                   "r"((b)[0]), "r"((b)[1]))

// ---------------- init -----------------------------------------------------------
__global__ void k_init() {
    int idx = blockIdx.x * blockDim.x + threadIdx.x;
    if (idx < NBR * BATCH * SEQ) ((float*)g_logit)[idx] = 0.0f;
    if (idx < NRD)               g_cnt[idx] = 0u;
}

// ---------------- pre-split tables ------------------------------------------------
__global__ void k_presplit_emb(const float* __restrict__ emb) {
    long long idx = (long long)blockIdx.x * blockDim.x + threadIdx.x;
    if (idx >= (long long)VOCAB * EKP) return;
    int row = (int)(idx / EKP), kp = (int)(idx % EKP);
    float2 v = (kp < 150) ? *(const float2*)(emb + (size_t)row * EDIM + 2 * kp)
                          : make_float2(0.0f, 0.0f);
    g_E2[idx] = split2h(v, 1.0f);
}
__global__ void k_presplit_wih(const float* __restrict__ Wih_f, const float* __restrict__ Wih_b) {
    long long idx = (long long)blockIdx.x * blockDim.x + threadIdx.x;
    if (idx >= (long long)NRD * GDIM * EKP) return;
    int kp = (int)(idx % EKP);
    int row = (int)((idx / EKP) % GDIM);
    int rd = (int)(idx / ((long long)GDIM * EKP));
    int branch = rd >> 1, dir = rd & 1;
    const float* W = (dir ? Wih_b : Wih_f) + (size_t)branch * GDIM * EDIM;
    float2 v = (kp < 150) ? *(const float2*)(W + (size_t)row * EDIM + 2 * kp)
                          : make_float2(0.0f, 0.0f);
    g_W2[idx] = split2h(v, WSCALE);
}
__global__ void k_presplit_wa(const float* __restrict__ Wa) {
    long long idx = (long long)blockIdx.x * blockDim.x + threadIdx.x;
    if (idx >= (long long)NBR * ADIM * 256) return;
    g_Wa2[idx] = split2h(*(const float2*)(Wa + 2 * idx), WSCALE);
}

// ---------------- phase 1: P = emb[x] @ Wih.T + bias  [fp16 2-term HMMA] ----------
__global__ void k_inputproj(const int* __restrict__ x,
                            const float* __restrict__ bih_f, const float* __restrict__ bhh_f,
                            const float* __restrict__ bih_b, const float* __restrict__ bhh_b) {
    __shared__ __align__(8) u32 As_s[2][128 * 20];
    __shared__ __align__(8) u32 Bs_s[2][64 * 20];
    __shared__ int tok[128];
    int mtile = blockIdx.x, ntile = blockIdx.y, rd = blockIdx.z;
    int branch = rd >> 1, dir = rd & 1;
    const float* bi  = (dir ? bih_b : bih_f) + branch * GDIM;
    const float* bh  = (dir ? bhh_b : bhh_f) + branch * GDIM;
    int tid = threadIdx.x;
    int m0 = mtile * 128, n0 = ntile * 64;
    if (tid < 128) {
        int m = m0 + tid;
        tok[tid] = x[(m & 63) * SEQ + (m >> 6)];
    }
    int lane = tid & 31, wid = tid >> 5;
    int g = lane >> 2, tg = lane & 3;
    int wm = wid & 3, wn = wid >> 2;
    int mbase = wm * 32, nbase = wn * 32;
    float C[2][4][4];
#pragma unroll
    for (int mt = 0; mt < 2; mt++)
#pragma unroll
        for (int nt = 0; nt < 4; nt++)
#pragma unroll
            for (int q = 0; q < 4; q++) C[mt][nt][q] = 0.0f;
    __syncthreads();

    {
#pragma unroll
        for (int i = 0; i < 4; i++) {
            int task = tid + i * 256;
            int m = task >> 3, kp = task & 7;
            *(ull*)&As_s[0][m * 20 + 2 * kp] = g_E2[(size_t)tok[m] * EKP + kp];
        }
#pragma unroll
        for (int i = 0; i < 2; i++) {
            int task = tid + i * 256;
            int n = task >> 3, kp = task & 7;
            *(ull*)&Bs_s[0][n * 20 + 2 * kp] = g_W2[((size_t)rd * GDIM + n0 + n) * EKP + kp];
        }
    }
    __syncthreads();

    int buf = 0;
    for (int k0 = 0; k0 < 304; k0 += 16) {
        if (k0 + 16 < 304) {
            int kb = (k0 + 16) >> 1;
#pragma unroll
            for (int i = 0; i < 4; i++) {
                int task = tid + i * 256;
                int m = task >> 3, kp = task & 7;
                *(ull*)&As_s[buf ^ 1][m * 20 + 2 * kp] = g_E2[(size_t)tok[m] * EKP + kb + kp];
            }
#pragma unroll
            for (int i = 0; i < 2; i++) {
                int task = tid + i * 256;
                int n = task >> 3, kp = task & 7;
                *(ull*)&Bs_s[buf ^ 1][n * 20 + 2 * kp] = g_W2[((size_t)rd * GDIM + n0 + n) * EKP + kb + kp];
            }
        }
        const u32* Ac = As_s[buf];
        const u32* Bc = Bs_s[buf];
        u32 Ahi[2][4], Bhi[4][2], Blo[4][2];
#pragma unroll
        for (int mt = 0; mt < 2; mt++) {
            int r0 = mbase + mt * 16 + g;
            ull v0 = *(const ull*)&Ac[r0 * 20 + 2 * tg];
            ull v1 = *(const ull*)&Ac[(r0 + 8) * 20 + 2 * tg];
            ull v2 = *(const ull*)&Ac[r0 * 20 + 2 * (tg + 4)];
            ull v3 = *(const ull*)&Ac[(r0 + 8) * 20 + 2 * (tg + 4)];
            Ahi[mt][0] = (u32)v0;
            Ahi[mt][1] = (u32)v1;
            Ahi[mt][2] = (u32)v2;
            Ahi[mt][3] = (u32)v3;
        }
#pragma unroll
        for (int nt = 0; nt < 4; nt++) {
            int n = nbase + nt * 8 + g;
            ull v0 = *(const ull*)&Bc[n * 20 + 2 * tg];
            ull v1 = *(const ull*)&Bc[n * 20 + 2 * (tg + 4)];
            Bhi[nt][0] = (u32)v0; Blo[nt][0] = (u32)(v0 >> 32);
            Bhi[nt][1] = (u32)v1; Blo[nt][1] = (u32)(v1 >> 32);
        }
#pragma unroll
        for (int mt = 0; mt < 2; mt++)
#pragma unroll
            for (int nt = 0; nt < 4; nt++) {
                MMA_F16(C[mt][nt], Ahi[mt], Bhi[nt]);
                MMA_F16(C[mt][nt], Ahi[mt], Blo[nt]);
            }
        __syncthreads();
        buf ^= 1;
    }
#pragma unroll
    for (int mt = 0; mt < 2; mt++)
#pragma unroll
        for (int rr = 0; rr < 2; rr++) {
            int m = m0 + mbase + mt * 16 + g + rr * 8;
            float* Pp = g_P + (((size_t)rd * SEQ + (m >> 6)) * BATCH + (m & 63)) * GDIM + n0 + nbase;
#pragma unroll
            for (int nt = 0; nt < 4; nt++) {
                int nl = nt * 8 + 2 * tg;
                int nf = n0 + nbase + nl;
                float2 o;
                o.x = C[mt][nt][rr * 2 + 0] * INVWS + bi[nf] + bh[nf];
                o.y = C[mt][nt][rr * 2 + 1] * INVWS + bi[nf + 1] + bh[nf + 1];
                *(float2*)(Pp + nl) = o;
            }
        }
}

// ---------------- phase 2: persistent recurrent scan  [fp16 2-term HMMA] ----------
#define A_CHUNK 1032            // words/chunk: 64 rows * 16 + 8 pad
#define B_CHUNK 2056            // words/chunk: 128 rows * 16 + 8 pad
#define SCAN_SMEM ((16 * A_CHUNK + 16 * B_CHUNK) * 4)   // 197,632 B

__global__ void __launch_bounds__(256, 1)
k_scan(const float* __restrict__ Whh_f, const float* __restrict__ Whh_b, int use_cluster) {
    extern __shared__ __align__(16) u32 smw[];
    u32* Bw = smw;                     // Whh split (scale 16), resident
    u32* Aw = smw + 16 * B_CHUNK;      // h split, restaged per step

    int rd = blockIdx.x >> 3;
    int blk = blockIdx.x & 7;
    int j0 = blk * 32;
    int branch = rd >> 1, dir = rd & 1;
    const float* W = (dir ? Whh_b : Whh_f) + (size_t)branch * GDIM * HDIM;
    int tid = threadIdx.x;
    int lane = tid & 31, wid = tid >> 5;
    int g = lane >> 2, tg = lane & 3;
    int wm = wid & 3, wn = wid >> 2;
    int mbase = wm * 16, nbase = wn * 64;
    int xg = g << 1;                   // xor swizzle key (rows ≡ g mod 8)

    // ---- stage Whh slice (permuted rows, fp16 split, scale 16), one time ----
    for (int p = tid; p < 128 * 128; p += 256) {
        int r = p >> 7;                 // n' 0..127
        int kpair = p & 127;
        int wnn = r >> 6, w = r & 63;
        int gate = w >> 4, jl = wnn * 16 + (w & 15);
        float2 v = *(const float2*)&W[(size_t)(gate * HDIM + j0 + jl) * HDIM + 2 * kpair];
        int idx = (kpair >> 3) * B_CHUNK + r * 16 + ((2 * (kpair & 7)) ^ ((r & 7) << 1));
        *(ull*)&Bw[idx] = split2h(v, WSCALE);
    }
    float c[2][4];                      // [rr][jh*2+q]
#pragma unroll
    for (int a = 0; a < 2; a++)
#pragma unroll
        for (int b = 0; b < 4; b++) c[a][b] = 0.0f;
    __syncthreads();

    for (int t = 0; t < SEQ; ++t) {
        int sidx = dir ? (SEQ - 1 - t) : t;
        // prefetch P preacts for this thread's 32 output units
        const float* Pb = g_P + ((size_t)rd * SEQ + sidx) * BATCH * GDIM;
        float2 Pr[2][2][4];             // [rr][jh][gate]
#pragma unroll
        for (int rr = 0; rr < 2; rr++) {
            int b = mbase + g + 8 * rr;
#pragma unroll
            for (int jh = 0; jh < 2; jh++) {
                int j = j0 + wn * 16 + jh * 8 + 2 * tg;
#pragma unroll
                for (int gate = 0; gate < 4; gate++)
                    Pr[rr][jh][gate] = *(const float2*)&Pb[(size_t)b * GDIM + gate * HDIM + j];
            }
        }

        // stage h(t-1) from g_HS2[sidx_prev] (zeros at t==0)
        if (t == 0) {
#pragma unroll
            for (int i = 0; i < 32; i++) {
                int p = tid + i * 256;
                int b = p >> 7, kpair = p & 127;
                int idx = (kpair >> 3) * A_CHUNK + b * 16 + ((2 * (kpair & 7)) ^ ((b & 7) << 1));
                *(ull*)&Aw[idx] = 0ull;
            }
        } else {
            int sidx_prev = dir ? (SEQ - t) : (t - 1);
            const ull* Hs = g_HS2 + ((size_t)rd * SEQ + sidx_prev) * BATCH * 128;
#pragma unroll
            for (int i = 0; i < 32; i++) {
                int p = tid + i * 256;
                int b = p >> 7, kpair = p & 127;
                ull v = __ldcv(&Hs[b * 128 + kpair]);
                int idx = (kpair >> 3) * A_CHUNK + b * 16 + ((2 * (kpair & 7)) ^ ((b & 7) << 1));
                *(ull*)&Aw[idx] = v;
            }
        }
        __syncthreads();

        float C[8][4];
#pragma unroll
        for (int nt = 0; nt < 8; nt++)
#pragma unroll
            for (int q = 0; q < 4; q++) C[nt][q] = 0.0f;

#pragma unroll 4
        for (int chunk = 0; chunk < 16; chunk++) {
            const u32* Ac = Aw + chunk * A_CHUNK;
            const u32* Bc = Bw + chunk * B_CHUNK;
            u32 Ahi[4];
            {
                int r0 = mbase + g;
                ull v0 = *(const ull*)&Ac[r0 * 16 + ((2 * tg) ^ xg)];
                ull v1 = *(const ull*)&Ac[(r0 + 8) * 16 + ((2 * tg) ^ xg)];
                ull v2 = *(const ull*)&Ac[r0 * 16 + ((2 * (tg + 4)) ^ xg)];
                ull v3 = *(const ull*)&Ac[(r0 + 8) * 16 + ((2 * (tg + 4)) ^ xg)];
                Ahi[0] = (u32)v0;
                Ahi[1] = (u32)v1;
                Ahi[2] = (u32)v2;
                Ahi[3] = (u32)v3;
            }
#pragma unroll
            for (int nt = 0; nt < 8; nt++) {
                int n = nbase + nt * 8 + g;
                ull v0 = *(const ull*)&Bc[n * 16 + ((2 * tg) ^ xg)];
                ull v1 = *(const ull*)&Bc[n * 16 + ((2 * (tg + 4)) ^ xg)];
                u32 Bhi[2], Blo[2];
                Bhi[0] = (u32)v0; Blo[0] = (u32)(v0 >> 32);
                Bhi[1] = (u32)v1; Blo[1] = (u32)(v1 >> 32);
                MMA_F16(C[nt], Ahi, Bhi);
                MMA_F16(C[nt], Ahi, Blo);
            }
        }

        // epilogue: gates (C * 1/16 + P) + cell update; h stored fp16-split
        ull* HSo = g_HS2 + ((size_t)rd * SEQ + sidx) * BATCH * 128;
#pragma unroll
        for (int rr = 0; rr < 2; rr++) {
            int b = mbase + g + 8 * rr;
#pragma unroll
            for (int jh = 0; jh < 2; jh++) {
                int j = j0 + wn * 16 + jh * 8 + 2 * tg;
                float iv0 = C[0 + jh][rr * 2 + 0] * INVWS + Pr[rr][jh][0].x;
                float fv0 = C[2 + jh][rr * 2 + 0] * INVWS + Pr[rr][jh][1].x;
                float gv0 = C[4 + jh][rr * 2 + 0] * INVWS + Pr[rr][jh][2].x;
                float ov0 = C[6 + jh][rr * 2 + 0] * INVWS + Pr[rr][jh][3].x;
                float iv1 = C[0 + jh][rr * 2 + 1] * INVWS + Pr[rr][jh][0].y;
                float fv1 = C[2 + jh][rr * 2 + 1] * INVWS + Pr[rr][jh][1].y;
                float gv1 = C[4 + jh][rr * 2 + 1] * INVWS + Pr[rr][jh][2].y;
                float ov1 = C[6 + jh][rr * 2 + 1] * INVWS + Pr[rr][jh][3].y;
                float cn0 = fsigm(fv0) * c[rr][jh * 2 + 0] + fsigm(iv0) * ftanh(gv0);
                float cn1 = fsigm(fv1) * c[rr][jh * 2 + 1] + fsigm(iv1) * ftanh(gv1);
                c[rr][jh * 2 + 0] = cn0;
                c[rr][jh * 2 + 1] = cn1;
                float2 hv;
                hv.x = fsigm(ov0) * ftanh(cn0);
                hv.y = fsigm(ov1) * ftanh(cn1);
                HSo[(size_t)b * 128 + (j >> 1)] = split2h(hv, 1.0f);
            }
        }
        // inter-block step barrier
        if (use_cluster) {
            asm volatile("barrier.cluster.arrive.aligned;" ::: "memory");
            asm volatile("barrier.cluster.wait.aligned;" ::: "memory");
        } else {
            __syncthreads();
            if (tid == 0) {
                asm volatile("red.release.gpu.global.add.u32 [%0], %1;"
                             :: "l"(&g_cnt[rd]), "r"(1u) : "memory");
                unsigned target = 8u * (unsigned)(t + 1), v;
                do {
                    asm volatile("ld.acquire.gpu.global.u32 %0, [%1];"
                                 : "=r"(v) : "l"(&g_cnt[rd]) : "memory");
                } while (v < target);
            }
            __syncthreads();
        }
    }
}

// ---------------- phase 3a: attention logits  [fp16 2-term HMMA] ------------------
__global__ void k_logits(const float* __restrict__ ba, const float* __restrict__ watt) {
    __shared__ __align__(8) u32 As_s[2][128 * 20];
    __shared__ __align__(8) u32 Bs_s[2][64 * 20];
    int mtile = blockIdx.x, ntile = blockIdx.y, br = blockIdx.z;
    int tid = threadIdx.x;
    int m0 = mtile * 128, n0 = ntile * 64;
    int lane = tid & 31, wid = tid >> 5;
    int g = lane >> 2, tg = lane & 3;
    int wm = wid & 3, wn = wid >> 2;
    int mbase = wm * 32, nbase = wn * 32;
    float C[2][4][4];
#pragma unroll
    for (int mt = 0; mt < 2; mt++)
#pragma unroll
        for (int nt = 0; nt < 4; nt++)
#pragma unroll
            for (int q = 0; q < 4; q++) C[mt][nt][q] = 0.0f;

    {
#pragma unroll
        for (int i = 0; i < 4; i++) {
            int task = tid + i * 256;
            int m = task >> 3, kp = task & 7;
            int mm = m0 + m;
            *(ull*)&As_s[0][m * 20 + 2 * kp] =
                g_HS2[(((size_t)(2 * br) * SEQ + (mm >> 6)) * BATCH + (mm & 63)) * 128 + kp];
        }
#pragma unroll
        for (int i = 0; i < 2; i++) {
            int task = tid + i * 256;
            int n = task >> 3, kp = task & 7;
            *(ull*)&Bs_s[0][n * 20 + 2 * kp] = g_Wa2[((size_t)br * ADIM + n0 + n) * 256 + kp];
        }
    }
    __syncthreads();

    int buf = 0;
    for (int k0 = 0; k0 < ADIM; k0 += 16) {
        if (k0 + 16 < ADIM) {
            int kn = k0 + 16;
            int rdh = 2 * br + (kn >> 8);
            int kbl = (kn & 255) >> 1;
#pragma unroll
            for (int i = 0; i < 4; i++) {
                int task = tid + i * 256;
                int m = task >> 3, kp = task & 7;
                int mm = m0 + m;
                *(ull*)&As_s[buf ^ 1][m * 20 + 2 * kp] =
                    g_HS2[(((size_t)rdh * SEQ + (mm >> 6)) * BATCH + (mm & 63)) * 128 + kbl + kp];
            }
#pragma unroll
            for (int i = 0; i < 2; i++) {
                int task = tid + i * 256;
                int n = task >> 3, kp = task & 7;
                *(ull*)&Bs_s[buf ^ 1][n * 20 + 2 * kp] =
                    g_Wa2[((size_t)br * ADIM + n0 + n) * 256 + (kn >> 1) + kp];
            }
        }
        const u32* Ac = As_s[buf];
        const u32* Bc = Bs_s[buf];
        u32 Ahi[2][4], Bhi[4][2], Blo[4][2];
#pragma unroll
        for (int mt = 0; mt < 2; mt++) {
            int r0 = mbase + mt * 16 + g;
            ull v0 = *(const ull*)&Ac[r0 * 20 + 2 * tg];
            ull v1 = *(const ull*)&Ac[(r0 + 8) * 20 + 2 * tg];
            ull v2 = *(const ull*)&Ac[r0 * 20 + 2 * (tg + 4)];
            ull v3 = *(const ull*)&Ac[(r0 + 8) * 20 + 2 * (tg + 4)];
            Ahi[mt][0] = (u32)v0;
            Ahi[mt][1] = (u32)v1;
            Ahi[mt][2] = (u32)v2;
            Ahi[mt][3] = (u32)v3;
        }
#pragma unroll
        for (int nt = 0; nt < 4; nt++) {
            int n = nbase + nt * 8 + g;
            ull v0 = *(const ull*)&Bc[n * 20 + 2 * tg];
            ull v1 = *(const ull*)&Bc[n * 20 + 2 * (tg + 4)];
            Bhi[nt][0] = (u32)v0; Blo[nt][0] = (u32)(v0 >> 32);
            Bhi[nt][1] = (u32)v1; Blo[nt][1] = (u32)(v1 >> 32);
        }
#pragma unroll
        for (int mt = 0; mt < 2; mt++)
#pragma unroll
            for (int nt = 0; nt < 4; nt++) {
                MMA_F16(C[mt][nt], Ahi[mt], Bhi[nt]);
                MMA_F16(C[mt][nt], Ahi[mt], Blo[nt]);
            }
        __syncthreads();
        buf ^= 1;
    }
#pragma unroll
    for (int mt = 0; mt < 2; mt++) {
        float p0 = 0.0f, p1 = 0.0f;
#pragma unroll
        for (int nt = 0; nt < 4; nt++) {
            int nf = n0 + nbase + nt * 8 + 2 * tg;
            float b0 = ba[br * ADIM + nf], w0 = watt[br * ADIM + nf];
            float b1 = ba[br * ADIM + nf + 1], w1 = watt[br * ADIM + nf + 1];
            p0 += ftanh(C[mt][nt][0] * INVWS + b0) * w0 + ftanh(C[mt][nt][1] * INVWS + b1) * w1;
            p1 += ftanh(C[mt][nt][2] * INVWS + b0) * w0 + ftanh(C[mt][nt][3] * INVWS + b1) * w1;
        }
        p0 += __shfl_xor_sync(0xffffffffu, p0, 1);
        p0 += __shfl_xor_sync(0xffffffffu, p0, 2);
        p1 += __shfl_xor_sync(0xffffffffu, p1, 1);
        p1 += __shfl_xor_sync(0xffffffffu, p1, 2);
        if (tg == 0) {
            int m = m0 + mbase + mt * 16 + g;
            atomicAdd(&g_logit[br][m & 63][m >> 6], p0);
            int m2 = m + 8;
            atomicAdd(&g_logit[br][m2 & 63][m2 >> 6], p1);
        }
    }
}

// ---------------- phase 3b: softmax over S -------------------------------------
__global__ void k_softmax() {
    int br = blockIdx.x >> 6, b = blockIdx.x & 63;
    __shared__ float red[256];
    const float* L = &g_logit[br][b][0];
    int tid = threadIdx.x;
    red[tid] = fmaxf(L[tid], L[tid + 256]); __syncthreads();
    for (int o = 128; o > 0; o >>= 1) { if (tid < o) red[tid] = fmaxf(red[tid], red[tid + o]); __syncthreads(); }
    float mx = red[0]; __syncthreads();
    float e0 = __expf(L[tid] - mx), e1 = __expf(L[tid + 256] - mx);
    red[tid] = e0 + e1; __syncthreads();
    for (int o = 128; o > 0; o >>= 1) { if (tid < o) red[tid] += red[tid + o]; __syncthreads(); }
    float inv = 1.0f / red[0];
    g_attw[br][b][tid] = e0 * inv;
    g_attw[br][b][tid + 256] = e1 * inv;
}

// ---------------- phase 3c: attention-weighted sum (reconstruct h = hi+lo) -------
__global__ void k_attsum() {
    int b = blockIdx.x, br = blockIdx.y;
    int d = threadIdx.x;
    __shared__ float aw[512];
    aw[d] = g_attw[br][b][d];
    __syncthreads();
    int rdh = (d < HDIM) ? (2 * br) : (2 * br + 1);
    int dd = d & 255;
    int kpair = dd >> 1, e = dd & 1;
    const ull* base = g_HS2 + (size_t)rdh * SEQ * BATCH * 128 + (size_t)b * 128 + kpair;
    float a0 = 0.0f, a1 = 0.0f;
    for (int s = 0; s < SEQ; s += 2) {
        ull v0 = base[(size_t)s * BATCH * 128];
        ull v1 = base[(size_t)(s + 1) * BATCH * 128];
        u32 hw0 = (u32)v0, lw0 = (u32)(v0 >> 32);
        u32 hw1 = (u32)v1, lw1 = (u32)(v1 >> 32);
        __half2 hh0 = *(__half2*)&hw0, ll0 = *(__half2*)&lw0;
        __half2 hh1 = *(__half2*)&hw1, ll1 = *(__half2*)&lw1;
        float h0 = e ? (__high2float(hh0) + __high2float(ll0))
                     : (__low2float(hh0) + __low2float(ll0));
        float h1 = e ? (__high2float(hh1) + __high2float(ll1))
                     : (__low2float(hh1) + __low2float(ll1));
        a0 = fmaf(aw[s],     h0, a0);
        a1 = fmaf(aw[s + 1], h1, a1);
    }
    g_ATT[br][b][d] = a0 + a1;
}

// ---------------- phase 4: routed final FC --------------------------------------
__global__ void k_final(const int* __restrict__ z, const float* __restrict__ Wfc,
                        const float* __restrict__ bfc, float* __restrict__ out) {
    int b = blockIdx.x;
    int tid = threadIdx.x;
    int zb = z[b];
    __shared__ float red0[256], red1[256];
    float a0 = 0.0f, a1 = 0.0f;
    for (int k = tid; k < 1024; k += 256) {
        float v = (k < 512) ? g_ATT[zb + 1][b][k] : g_ATT[0][b][k - 512];
        a0 = fmaf(v, Wfc[k], a0);
        a1 = fmaf(v, Wfc[1024 + k], a1);
    }
    red0[tid] = a0; red1[tid] = a1; __syncthreads();
    for (int o = 128; o > 0; o >>= 1) {
        if (tid < o) { red0[tid] += red0[tid + o]; red1[tid] += red1[tid + o]; }
        __syncthreads();
    }
    if (tid == 0) {
        out[b * 2 + 0] = red0[0] + bfc[0];
        out[b * 2 + 1] = red1[0] + bfc[1];
    }
}

// ---------------- copy general + specifics into d_out ---------------------------
__global__ void k_copyout(float* __restrict__ out) {
    int idx = blockIdx.x * blockDim.x + threadIdx.x;
    if (idx < NBR * BATCH * ADIM) out[128 + idx] = (&g_ATT[0][0][0])[idx];
}

// ---------------- launcher -------------------------------------------------------
extern "C" void kernel_launch(void* const* d_in, const int* in_sizes, int n_in,
                              void* d_out, int out_size) {
    const int*   x     = (const int*)  d_in[0];
    const int*   z     = (const int*)  d_in[1];
    const float* emb   = (const float*)d_in[2];
    const float* Wih_f = (const float*)d_in[3];
    const float* Whh_f = (const float*)d_in[4];
    const float* bih_f = (const float*)d_in[5];
    const float* bhh_f = (const float*)d_in[6];
    const float* Wih_b = (const float*)d_in[7];
    const float* Whh_b = (const float*)d_in[8];
    const float* bih_b = (const float*)d_in[9];
    const float* bhh_b = (const float*)d_in[10];
    const float* Wa    = (const float*)d_in[11];
    const float* ba    = (const float*)d_in[12];
    const float* watt  = (const float*)d_in[13];
    const float* Wfc   = (const float*)d_in[14];
    const float* bfc   = (const float*)d_in[15];
    float* out = (float*)d_out;

    cudaFuncSetAttribute(k_scan, cudaFuncAttributeMaxDynamicSharedMemorySize, SCAN_SMEM);

    k_init<<<1280, 256>>>();
    k_presplit_emb<<<(VOCAB * EKP + 255) / 256, 256>>>(emb);
    k_presplit_wih<<<(NRD * GDIM * EKP + 255) / 256, 256>>>(Wih_f, Wih_b);
    k_presplit_wa<<<(NBR * ADIM * 256 + 255) / 256, 256>>>(Wa);
    k_inputproj<<<dim3(256, 16, 10), 256>>>(x, bih_f, bhh_f, bih_b, bhh_b);

    // scan: try cluster launch (10 clusters of 8); fall back to atomic barrier
    {
        cudaLaunchConfig_t cfg = {};
        cfg.gridDim = dim3(80, 1, 1);
        cfg.blockDim = dim3(256, 1, 1);
        cfg.dynamicSmemBytes = SCAN_SMEM;
        cudaLaunchAttribute attrs[1];
        attrs[0].id = cudaLaunchAttributeClusterDimension;
        attrs[0].val.clusterDim = {8, 1, 1};
        cfg.attrs = attrs;
        cfg.numAttrs = 1;
        cudaError_t err = cudaLaunchKernelEx(&cfg, k_scan, Whh_f, Whh_b, 1);
        if (err != cudaSuccess) {
            (void)cudaGetLastError();   // clear
            k_scan<<<80, 256, SCAN_SMEM>>>(Whh_f, Whh_b, 0);
        }
    }

    k_logits<<<dim3(256, 8, 5), 256>>>(ba, watt);
    k_softmax<<<320, 256>>>();
    k_attsum<<<dim3(64, 5), 512>>>();
    k_final<<<64, 256>>>(z, Wfc, bfc, out);
    k_copyout<<<640, 256>>>(out);
}